// round 14
// baseline (speedup 1.0000x reference)
#include <cuda_runtime.h>
#include <cuda_fp16.h>
#include <math.h>

// Problem constants
#define BATCH 16
#define DQ    768
#define NQ    1024
#define NT    64
#define DKV   384
#define NH    12
#define HD    64
#define NKV   (BATCH*NT)
#define DKV2  (2*DQ)

#define NEG_L2B_32 (-0.41524101186091903f)   // -log2(10000)/32

typedef unsigned short u16;
typedef unsigned int   u32;

// ---------------------------------------------------------------------------
// Scratch (device globals)
// ---------------------------------------------------------------------------
__device__ __align__(16) u16 g_qin_h[(size_t)BATCH*NQ*DQ];     // feat^T hi fp16
__device__ __align__(16) u16 g_k_h  [(size_t)BATCH*NH*NT*HD];  // rope'd K hi [b,h,t,hd]
__device__ __align__(16) u16 g_vT_h [(size_t)BATCH*NH*HD*NT];  // V^T hi [b,h,hd,t]
__device__ __align__(16) u16 g_o_h  [(size_t)BATCH*NQ*DQ];     // attn out hi [B,Nq,Dq]
__device__ __align__(16) u16 g_wq_h [DQ*DQ];                   // WqT hi
__device__ __align__(16) u16 g_wkv_h[DKV2*DKV];                // WkvT hi
__device__ __align__(16) u16 g_wo_h [DQ*DQ];                   // WoutT hi
__device__ __align__(16) u16 g_tok_h[NKV*DKV];                 // tokens hi
__device__ __align__(16) float2 g_cs[NQ*32];                   // (cos, sin)

// dependency counters (reset in-kernel by last CTA; zero-init at module load)
__device__ u32 c_wq = 0, c_wkv = 0, c_wo = 0, c_tok = 0, c_rope = 0;
__device__ u32 c_feat[BATCH];
__device__ u32 g_kvflag = 0;
__device__ u32 g_qdone[BATCH * 8];
__device__ u32 g_alldone = 0;

// grid layout
#define NB_WQ   576
#define NB_WKV  576
#define NB_WO   576
#define NB_TOK  384
#define NB_ROPE 128
#define NB_FEAT 3072          // 16 batches x 192
#define O_WKV   (NB_WQ)
#define O_WO    (O_WKV + NB_WKV)
#define O_TOK   (O_WO + NB_WO)
#define O_ROPE  (O_TOK + NB_TOK)
#define O_FEAT  (O_ROPE + NB_ROPE)
#define O_KV    (O_FEAT + NB_FEAT)        // 5312
#define O_Q     (O_KV + 96)               // 5408
#define O_OUT   (O_Q + 768)               // 6176
#define NB_ALL  (O_OUT + 768)             // 6944

// ---------------------------------------------------------------------------
// Helpers (base-ISA only)
// ---------------------------------------------------------------------------
__device__ __forceinline__ u32 smem_u32(const void* p) {
    u32 a;
    asm("{ .reg .u64 t; cvta.to.shared.u64 t, %1; cvt.u32.u64 %0, t; }" : "=r"(a) : "l"(p));
    return a;
}
__device__ __forceinline__ u32 swz(u32 o) { return o ^ ((o >> 3) & 0x70); }

__device__ __forceinline__ void cpa16(u32 s, const void* g) {
    asm volatile("cp.async.cg.shared.global [%0], [%1], 16;" :: "r"(s), "l"(g) : "memory");
}
#define CP_COMMIT() asm volatile("cp.async.commit_group;" ::: "memory")
#define CP_WAIT(n)  asm volatile("cp.async.wait_group %0;" :: "n"(n) : "memory")

__device__ __forceinline__ void ldsm4(u32* r, u32 a) {
    asm volatile("ldmatrix.sync.aligned.m8n8.x4.shared.b16 {%0,%1,%2,%3}, [%4];"
                 : "=r"(r[0]), "=r"(r[1]), "=r"(r[2]), "=r"(r[3]) : "r"(a));
}
__device__ __forceinline__ void mma16816(float* c, const u32* a, const u32* b) {
    asm volatile(
        "mma.sync.aligned.m16n8k16.row.col.f32.f16.f16.f32 "
        "{%0,%1,%2,%3}, {%4,%5,%6,%7}, {%8,%9}, {%0,%1,%2,%3};"
        : "+f"(c[0]), "+f"(c[1]), "+f"(c[2]), "+f"(c[3])
        : "r"(a[0]), "r"(a[1]), "r"(a[2]), "r"(a[3]), "r"(b[0]), "r"(b[1]));
}

__device__ __forceinline__ u16 f16h(float v) {
    __half h = __float2half_rn(v);
    return *reinterpret_cast<u16*>(&h);
}
__device__ __forceinline__ u32 pack_h(float a, float b) {
    __half2 h = __float22half2_rn(make_float2(a, b));
    return *reinterpret_cast<u32*>(&h);
}

__device__ __forceinline__ void publish(u32* f) {
    __threadfence();
    __syncthreads();
    if (threadIdx.x == 0) atomicAdd(f, 1u);
}
__device__ __forceinline__ void wait_ge(volatile u32* f, u32 target) {
    if (threadIdx.x == 0) {
        while (*f < target) __nanosleep(64);
        __threadfence();
    }
    __syncthreads();
}

// ---------------------------------------------------------------------------
// Conversion tile helpers
// ---------------------------------------------------------------------------
__device__ __forceinline__ void convT_tile(const float* __restrict__ in,
                                           u16* __restrict__ oh,
                                           int R, int C, int bx, int by,
                                           float (*t)[33])
{
    int txx = threadIdx.x & 31, tyy = threadIdx.x >> 5;
    int x = bx * 32 + txx;
    int y0 = by * 32 + tyy;
    #pragma unroll
    for (int i = 0; i < 32; i += 8)
        t[tyy + i][txx] = in[(size_t)(y0 + i) * C + x];
    __syncthreads();
    int orow0 = bx * 32 + tyy;
    int ocol  = by * 32 + txx;
    #pragma unroll
    for (int i = 0; i < 32; i += 8)
        oh[(size_t)(orow0 + i) * R + ocol] = f16h(t[txx][tyy + i]);
}

__device__ __forceinline__ void conv_feat64(const float* __restrict__ in,
                                            u16* __restrict__ out,
                                            int bd, int bn, float (*t)[65])
{
    const int tid = threadIdx.x;
    #pragma unroll
    for (int it = 0; it < 4; it++) {
        int idx = it * 256 + tid;
        int r = idx >> 4, c4 = idx & 15;
        float4 v = *(const float4*)(in + (size_t)(bd * 64 + r) * NQ + bn * 64 + c4 * 4);
        t[r][c4 * 4 + 0] = v.x; t[r][c4 * 4 + 1] = v.y;
        t[r][c4 * 4 + 2] = v.z; t[r][c4 * 4 + 3] = v.w;
    }
    __syncthreads();
    #pragma unroll
    for (int it = 0; it < 2; it++) {
        int idx = it * 256 + tid;
        int r = idx >> 3, c = idx & 7;
        u32 w0 = pack_h(t[c * 8 + 0][r], t[c * 8 + 1][r]);
        u32 w1 = pack_h(t[c * 8 + 2][r], t[c * 8 + 3][r]);
        u32 w2 = pack_h(t[c * 8 + 4][r], t[c * 8 + 5][r]);
        u32 w3 = pack_h(t[c * 8 + 6][r], t[c * 8 + 7][r]);
        *(uint4*)(out + (size_t)(bn * 64 + r) * DQ + bd * 64 + c * 8) =
            make_uint4(w0, w1, w2, w3);
    }
}

// ---------------------------------------------------------------------------
// Shared GEMM config
// ---------------------------------------------------------------------------
#define BK 64
#define STG 32768
#define AH_O 0
#define BH_O 16384
#define GSMEM (3*STG)
#define QOFF 0
#define KOFF 32768
#define VOFF 49152

#define LOAD_STAGE(kt, slot) do {                                                \
    u32 so_ = sbase + (u32)(slot) * STG;                                         \
    int k0_ = (kt) * BK;                                                         \
    _Pragma("unroll")                                                            \
    for (int i_ = 0; i_ < 4; i_++) {                                             \
        int chunk_ = i_ * 256 + tid;                                             \
        int row_ = chunk_ >> 3, c_ = chunk_ & 7;                                 \
        u32 off_ = swz((u32)(row_ * 128 + c_ * 16));                             \
        size_t ga_ = (size_t)(m0 + row_) * K + k0_ + c_ * 8;                     \
        size_t gb_ = (size_t)(n0 + row_) * K + k0_ + c_ * 8;                     \
        cpa16(so_ + AH_O + off_, Ahb + ga_);                                     \
        cpa16(so_ + BH_O + off_, Bhb + gb_);                                     \
    }                                                                            \
} while (0)

#define LOAD_FRAGS(buf, sa, ks) do {                                             \
    _Pragma("unroll")                                                            \
    for (int mi_ = 0; mi_ < 2; mi_++) {                                          \
        int row_ = wm + mi_ * 16 + (lane & 15);                                  \
        int chunk_ = 2 * (ks) + (lane >> 4);                                     \
        ldsm4(ahf[buf][mi_], (sa) + AH_O + swz((u32)(row_ * 128 + chunk_ * 16))); \
    }                                                                            \
    _Pragma("unroll")                                                            \
    for (int jj_ = 0; jj_ < 4; jj_++) {                                          \
        int g_ = lane >> 3;                                                      \
        int row_ = wn + (2 * jj_ + (g_ >> 1)) * 8 + (lane & 7);                  \
        int chunk_ = 2 * (ks) + (g_ & 1);                                        \
        u32 t_[4];                                                               \
        ldsm4(t_, (sa) + BH_O + swz((u32)(row_ * 128 + chunk_ * 16)));           \
        bhf[buf][2*jj_][0] = t_[0]; bhf[buf][2*jj_][1] = t_[1];                  \
        bhf[buf][2*jj_+1][0] = t_[2]; bhf[buf][2*jj_+1][1] = t_[3];              \
    }                                                                            \
} while (0)

#define GEMM_MAINLOOP                                                            \
    float acc[2][8][4];                                                          \
    _Pragma("unroll")                                                            \
    for (int i = 0; i < 2; i++)                                                  \
        _Pragma("unroll")                                                        \
        for (int j = 0; j < 8; j++)                                              \
            _Pragma("unroll")                                                    \
            for (int p = 0; p < 4; p++) acc[i][j][p] = 0.f;                      \
    const int KT = K / BK;                                                       \
    LOAD_STAGE(0, 0);                                                            \
    CP_COMMIT();                                                                 \
    if (KT > 1) { LOAD_STAGE(1, 1); CP_COMMIT(); }                               \
    u32 ahf[2][2][4], bhf[2][8][2];                                              \
    int slot = 0;                                                                \
    for (int kt = 0; kt < KT; kt++) {                                            \
        if (kt + 1 < KT) CP_WAIT(1); else CP_WAIT(0);                            \
        __syncthreads();                                                         \
        if (kt + 2 < KT) {                                                       \
            int ns = slot + 2; if (ns >= 3) ns -= 3;                             \
            LOAD_STAGE(kt + 2, ns);                                              \
            CP_COMMIT();                                                         \
        }                                                                        \
        const u32 sa = sbase + (u32)slot * STG;                                  \
        LOAD_FRAGS(0, sa, 0);                                                    \
        _Pragma("unroll")                                                        \
        for (int ks = 0; ks < 4; ks++) {                                         \
            const int cur = ks & 1;                                              \
            if (ks < 3) LOAD_FRAGS(!cur ? 1 : 0, sa, ks + 1);                    \
            _Pragma("unroll")                                                    \
            for (int mi = 0; mi < 2; mi++)                                       \
                _Pragma("unroll")                                                \
                for (int ni = 0; ni < 8; ni++)                                   \
                    mma16816(acc[mi][ni], ahf[cur][mi], bhf[cur][ni]);           \
        }                                                                        \
        slot++; if (slot >= 3) slot = 0;                                         \
    }

// ---------------------------------------------------------------------------
// THE kernel: conv (weights/tok/rope/feat) -> kv-proj -> q-proj+attn -> out-proj
// Single 1D grid; in-order dispatch makes every wait target lower-bid CTAs.
// ---------------------------------------------------------------------------
__global__ void __launch_bounds__(256, 2)
megakernel(const float* __restrict__ Wqf, const float* __restrict__ Wkvf,
           const float* __restrict__ Wof, const float* __restrict__ tokf,
           const float* __restrict__ featf,
           float* __restrict__ C, const float* __restrict__ Bias)
{
    extern __shared__ char smdyn[];
    const u32 sbase = smem_u32(smdyn);
    const int tid  = threadIdx.x;
    const int lane = tid & 31;
    const int wid  = tid >> 5;
    const int wm   = (wid & 3) * 32;
    const int wn   = (wid >> 2) * 64;
    const int gbid = blockIdx.x;

    if (gbid < O_KV) {
        // ===================== conversion classes =====================
        if (gbid < NB_WQ) {
            convT_tile(Wqf, g_wq_h, DQ, DQ, gbid % 24, gbid / 24, (float(*)[33])smdyn);
            publish(&c_wq);
        } else if (gbid < O_WO) {
            int i = gbid - O_WKV;
            convT_tile(Wkvf, g_wkv_h, DKV, DKV2, i % 48, i / 48, (float(*)[33])smdyn);
            publish(&c_wkv);
        } else if (gbid < O_TOK) {
            int i = gbid - O_WO;
            convT_tile(Wof, g_wo_h, DQ, DQ, i % 24, i / 24, (float(*)[33])smdyn);
            publish(&c_wo);
        } else if (gbid < O_ROPE) {
            int base = (gbid - O_TOK) * 1024 + tid * 4;
            float4 v = *(const float4*)(tokf + base);
            *(u32*)&g_tok_h[base]     = pack_h(v.x, v.y);
            *(u32*)&g_tok_h[base + 2] = pack_h(v.z, v.w);
            publish(&c_tok);
        } else if (gbid < O_FEAT) {
            int idx = (gbid - O_ROPE) * 256 + tid;
            int pos = idx >> 5, i = idx & 31;
            float inv = exp2f((float)i * NEG_L2B_32);
            float sn, cs;
            sincosf((float)pos * inv, &sn, &cs);
            g_cs[idx] = make_float2(cs, sn);
            publish(&c_rope);
        } else {
            int i = gbid - O_FEAT;        // batch-major: b = i/192
            int b = i / 192;
            int rem = i % 192;
            int bd = rem >> 4;
            int bn = rem & 15;
            conv_feat64(featf + (size_t)b * DQ * NQ, g_qin_h + (size_t)b * NQ * DQ,
                        bd, bn, (float(*)[65])smdyn);
            publish(&c_feat[b]);
        }
    } else {
        // ===================== GEMM classes =====================
        const int cls = (gbid < O_Q) ? 0 : (gbid < O_OUT ? 1 : 2);
        int m0, n0, bz, K;
        const u16 *Ahb, *Bhb;
        if (cls == 0) {
            int i = gbid - O_KV;
            n0 = (i % 12) * 128;
            m0 = (i / 12) * 128;
            bz = 0;
            Ahb = g_tok_h; Bhb = g_wkv_h; K = DKV;
            wait_ge(&c_tok, NB_TOK);
            wait_ge(&c_wkv, NB_WKV);
            wait_ge(&c_rope, NB_ROPE);
        } else if (cls == 1) {
            int i = gbid - O_Q;
            bz = i / 48;
            int rem = i % 48;
            m0 = (rem / 6) * 128;
            n0 = (rem % 6) * 128;
            Ahb = g_qin_h + (size_t)bz * NQ * DQ; Bhb = g_wq_h; K = DQ;
            wait_ge(&c_feat[bz], 192);
            wait_ge(&c_wq, NB_WQ);
            wait_ge(&c_rope, NB_ROPE);
        } else {
            int i = gbid - O_OUT;
            bz = i / 48;
            int rem = i % 48;
            m0 = (rem % 6) * 128;
            n0 = (rem / 6) * 128;
            Ahb = g_wo_h; Bhb = g_o_h + (size_t)bz * NQ * DQ; K = DQ;
            wait_ge(&c_wo, NB_WO);
            wait_ge(&g_qdone[bz * 8 + (n0 >> 7)], 6);
        }

        GEMM_MAINLOOP

        if (cls == 0) {
            // ---- kv epilogue ----
            if (n0 + wn < DQ) {
                #pragma unroll
                for (int mi = 0; mi < 2; mi++)
                    #pragma unroll
                    for (int ni = 0; ni < 4; ni++)
                        #pragma unroll
                        for (int half = 0; half < 2; half++) {
                            int m = m0 + wm + mi * 16 + (lane >> 2) + half * 8;
                            int bb = m >> 6, t = m & 63;
                            int n = n0 + wn + ni * 8 + (lane & 3) * 2;
                            int h = n >> 6;
                            int i0 = n & 63;
                            float2 cs0 = g_cs[t * 32 + i0];
                            float2 cs1 = g_cs[t * 32 + i0 + 1];
                            float x1a = acc[mi][ni][half*2],   x2a = acc[mi][ni+4][half*2];
                            float x1b = acc[mi][ni][half*2+1], x2b = acc[mi][ni+4][half*2+1];
                            float y1a = x1a * cs0.x - x2a * cs0.y;
                            float y2a = x2a * cs0.x + x1a * cs0.y;
                            float y1b = x1b * cs1.x - x2b * cs1.y;
                            float y2b = x2b * cs1.x + x1b * cs1.y;
                            size_t base = (((size_t)bb * NH + h) * NT + t) * HD;
                            *(u32*)&g_k_h[base + i0]      = pack_h(y1a, y1b);
                            *(u32*)&g_k_h[base + i0 + 32] = pack_h(y2a, y2b);
                        }
            } else {
                #pragma unroll
                for (int mi = 0; mi < 2; mi++)
                    #pragma unroll
                    for (int ni = 0; ni < 8; ni++)
                        #pragma unroll
                        for (int p = 0; p < 4; p++) {
                            int m = m0 + wm + mi * 16 + (lane >> 2) + (p >> 1) * 8;
                            int bb = m >> 6, t = m & 63;
                            int n = n0 + wn + ni * 8 + (lane & 3) * 2 + (p & 1);
                            int h = (n - DQ) >> 6;
                            int hd = n & 63;
                            size_t o = (((size_t)bb * NH + h) * HD + hd) * NT + t;
                            g_vT_h[o] = f16h(acc[mi][ni][p]);
                        }
            }
            publish(&g_kvflag);
        } else if (cls == 2) {
            // ---- out epilogue ----
            #pragma unroll
            for (int mi = 0; mi < 2; mi++)
                #pragma unroll
                for (int ni = 0; ni < 8; ni++) {
                    int m = m0 + wm + mi * 16 + (lane >> 2);
                    int n = n0 + wn + ni * 8 + (lane & 3) * 2;
                    const float* c = acc[mi][ni];
                    size_t a0 = ((size_t)bz * DQ + m) * NQ + n;
                    size_t a1 = ((size_t)bz * DQ + m + 8) * NQ + n;
                    float b0 = Bias[m], b1 = Bias[m + 8];
                    float2 f0 = *(const float2*)&featf[a0];
                    float2 f1 = *(const float2*)&featf[a1];
                    *(float2*)&C[a0] = make_float2(c[0] + f0.x + b0, c[1] + f0.y + b0);
                    *(float2*)&C[a1] = make_float2(c[2] + f1.x + b1, c[3] + f1.y + b1);
                }
        } else {
            // ---- q epilogue: RoPE -> smem, wait kv, attention, publish ----
            __syncthreads();

            const int hh_w = wid >> 2;
            const u32 qbase = sbase + QOFF + (u32)hh_w * 16384;
            #pragma unroll
            for (int mi = 0; mi < 2; mi++)
                #pragma unroll
                for (int ni = 0; ni < 4; ni++)
                    #pragma unroll
                    for (int half = 0; half < 2; half++) {
                        int m_loc = wm + mi * 16 + (lane >> 2) + half * 8;
                        int m = m0 + m_loc;
                        int i0 = ni * 8 + (lane & 3) * 2;
                        float2 cs0 = g_cs[m * 32 + i0];
                        float2 cs1 = g_cs[m * 32 + i0 + 1];
                        float x1a = acc[mi][ni][half*2],   x2a = acc[mi][ni+4][half*2];
                        float x1b = acc[mi][ni][half*2+1], x2b = acc[mi][ni+4][half*2+1];
                        float y1a = x1a * cs0.x - x2a * cs0.y;
                        float y2a = x2a * cs0.x + x1a * cs0.y;
                        float y1b = x1b * cs1.x - x2b * cs1.y;
                        float y2b = x2b * cs1.x + x1b * cs1.y;
                        asm volatile("st.shared.u32 [%0], %1;" ::
                            "r"(qbase + swz((u32)(m_loc * 128 + i0 * 2))), "r"(pack_h(y1a, y1b)));
                        asm volatile("st.shared.u32 [%0], %1;" ::
                            "r"(qbase + swz((u32)(m_loc * 128 + (i0 + 32) * 2))), "r"(pack_h(y2a, y2b)));
                    }

            wait_ge(&g_kvflag, 96);

            const int hbase = n0 >> 6;
            {
                size_t kvb = ((size_t)bz * NH + hbase) * (NT * HD);
                #pragma unroll
                for (int i = 0; i < 4; i++) {
                    int c = i * 256 + tid;
                    int hh = c >> 9;
                    int r  = (c >> 3) & 63;
                    int cc = c & 7;
                    u32 off = (u32)hh * 8192 + swz((u32)(r * 128 + cc * 16));
                    cpa16(sbase + KOFF + off, g_k_h  + kvb + (size_t)hh * (NT*HD) + r * HD + cc * 8);
                    cpa16(sbase + VOFF + off, g_vT_h + kvb + (size_t)hh * (NT*HD) + r * HD + cc * 8);
                }
                CP_COMMIT();
                CP_WAIT(0);
                __syncthreads();
            }

            const u32 kbase = sbase + KOFF + (u32)hh_w * 8192;
            const u32 vbase = sbase + VOFF + (u32)hh_w * 8192;
            const int qw = (wid & 3) * 32;

            float s[2][8][4];
            #pragma unroll
            for (int i = 0; i < 2; i++)
                #pragma unroll
                for (int j = 0; j < 8; j++)
                    #pragma unroll
                    for (int p = 0; p < 4; p++) s[i][j][p] = 0.f;

            #pragma unroll
            for (int ks = 0; ks < 4; ks++) {
                u32 aq[2][4], bk[8][2];
                #pragma unroll
                for (int mi = 0; mi < 2; mi++) {
                    int row = qw + mi * 16 + (lane & 15);
                    int chunk = 2 * ks + (lane >> 4);
                    ldsm4(aq[mi], qbase + swz((u32)(row * 128 + chunk * 16)));
                }
                #pragma unroll
                for (int jj = 0; jj < 4; jj++) {
                    int g = lane >> 3;
                    int row = (2 * jj + (g >> 1)) * 8 + (lane & 7);
                    int chunk = 2 * ks + (g & 1);
                    u32 t[4];
                    ldsm4(t, kbase + swz((u32)(row * 128 + chunk * 16)));
                    bk[2*jj][0] = t[0]; bk[2*jj][1] = t[1];
                    bk[2*jj+1][0] = t[2]; bk[2*jj+1][1] = t[3];
                }
                #pragma unroll
                for (int mi = 0; mi < 2; mi++)
                    #pragma unroll
                    for (int ni = 0; ni < 8; ni++)
                        mma16816(s[mi][ni], aq[mi], bk[ni]);
            }

            // softmax (scale 1/8)
            #pragma unroll
            for (int mi = 0; mi < 2; mi++) {
                float mx0 = -1e30f, mx1 = -1e30f;
                #pragma unroll
                for (int ni = 0; ni < 8; ni++) {
                    #pragma unroll
                    for (int p = 0; p < 4; p++) s[mi][ni][p] *= 0.125f;
                    mx0 = fmaxf(mx0, fmaxf(s[mi][ni][0], s[mi][ni][1]));
                    mx1 = fmaxf(mx1, fmaxf(s[mi][ni][2], s[mi][ni][3]));
                }
                mx0 = fmaxf(mx0, __shfl_xor_sync(0xffffffffu, mx0, 1));
                mx0 = fmaxf(mx0, __shfl_xor_sync(0xffffffffu, mx0, 2));
                mx1 = fmaxf(mx1, __shfl_xor_sync(0xffffffffu, mx1, 1));
                mx1 = fmaxf(mx1, __shfl_xor_sync(0xffffffffu, mx1, 2));
                float sm0 = 0.f, sm1 = 0.f;
                #pragma unroll
                for (int ni = 0; ni < 8; ni++) {
                    s[mi][ni][0] = __expf(s[mi][ni][0] - mx0);
                    s[mi][ni][1] = __expf(s[mi][ni][1] - mx0);
                    s[mi][ni][2] = __expf(s[mi][ni][2] - mx1);
                    s[mi][ni][3] = __expf(s[mi][ni][3] - mx1);
                    sm0 += s[mi][ni][0] + s[mi][ni][1];
                    sm1 += s[mi][ni][2] + s[mi][ni][3];
                }
                sm0 += __shfl_xor_sync(0xffffffffu, sm0, 1);
                sm0 += __shfl_xor_sync(0xffffffffu, sm0, 2);
                sm1 += __shfl_xor_sync(0xffffffffu, sm1, 1);
                sm1 += __shfl_xor_sync(0xffffffffu, sm1, 2);
                float i0 = 1.f / sm0, i1 = 1.f / sm1;
                #pragma unroll
                for (int ni = 0; ni < 8; ni++) {
                    s[mi][ni][0] *= i0; s[mi][ni][1] *= i0;
                    s[mi][ni][2] *= i1; s[mi][ni][3] *= i1;
                }
            }

            // O = P V
            float o[2][8][4];
            #pragma unroll
            for (int i = 0; i < 2; i++)
                #pragma unroll
                for (int j = 0; j < 8; j++)
                    #pragma unroll
                    for (int p = 0; p < 4; p++) o[i][j][p] = 0.f;

            #pragma unroll
            for (int kc = 0; kc < 4; kc++) {
                u32 pah[2][4], bv[8][2];
                #pragma unroll
                for (int mi = 0; mi < 2; mi++) {
                    pah[mi][0] = pack_h(s[mi][2*kc][0],   s[mi][2*kc][1]);
                    pah[mi][1] = pack_h(s[mi][2*kc][2],   s[mi][2*kc][3]);
                    pah[mi][2] = pack_h(s[mi][2*kc+1][0], s[mi][2*kc+1][1]);
                    pah[mi][3] = pack_h(s[mi][2*kc+1][2], s[mi][2*kc+1][3]);
                }
                #pragma unroll
                for (int jj = 0; jj < 4; jj++) {
                    int g = lane >> 3;
                    int row = (2 * jj + (g >> 1)) * 8 + (lane & 7);
                    int chunk = 2 * kc + (g & 1);
                    u32 t[4];
                    ldsm4(t, vbase + swz((u32)(row * 128 + chunk * 16)));
                    bv[2*jj][0] = t[0]; bv[2*jj][1] = t[1];
                    bv[2*jj+1][0] = t[2]; bv[2*jj+1][1] = t[3];
                }
                #pragma unroll
                for (int mi = 0; mi < 2; mi++)
                    #pragma unroll
                    for (int ni = 0; ni < 8; ni++)
                        mma16816(o[mi][ni], pah[mi], bv[ni]);
            }

            #pragma unroll
            for (int mi = 0; mi < 2; mi++)
                #pragma unroll
                for (int ni = 0; ni < 8; ni++) {
                    int q = m0 + qw + mi * 16 + (lane >> 2);
                    int col = n0 + hh_w * 64 + ni * 8 + (lane & 3) * 2;
                    size_t a0 = ((size_t)(bz * NQ + q)) * DQ + col;
                    size_t a1 = ((size_t)(bz * NQ + q + 8)) * DQ + col;
                    *(u32*)&g_o_h[a0] = pack_h(o[mi][ni][0], o[mi][ni][1]);
                    *(u32*)&g_o_h[a1] = pack_h(o[mi][ni][2], o[mi][ni][3]);
                }
            publish(&g_qdone[bz * 8 + (m0 >> 7)]);
        }
    }

    // ---- terminal: last CTA resets all flags for the next graph replay ----
    __syncthreads();
    if (tid == 0) {
        u32 old = atomicAdd(&g_alldone, 1u);
        if (old == NB_ALL - 1) {
            c_wq = 0; c_wkv = 0; c_wo = 0; c_tok = 0; c_rope = 0;
            #pragma unroll
            for (int i = 0; i < BATCH; i++) c_feat[i] = 0;
            g_kvflag = 0;
            for (int i = 0; i < BATCH * 8; i++) g_qdone[i] = 0;
            __threadfence();
            g_alldone = 0;
        }
    }
}

// ---------------------------------------------------------------------------
// Launch
// ---------------------------------------------------------------------------
extern "C" void kernel_launch(void* const* d_in, const int* in_sizes, int n_in,
                              void* d_out, int out_size)
{
    (void)in_sizes; (void)n_in; (void)out_size;
    const float* feat   = (const float*)d_in[0];
    const float* tokens = (const float*)d_in[1];
    const float* Wq     = (const float*)d_in[2];
    const float* Wkv    = (const float*)d_in[3];
    const float* Wout   = (const float*)d_in[4];
    const float* bout   = (const float*)d_in[5];
    float* outp = (float*)d_out;

    cudaFuncSetAttribute(megakernel, cudaFuncAttributeMaxDynamicSharedMemorySize, GSMEM);

    megakernel<<<NB_ALL, 256, GSMEM>>>(Wq, Wkv, Wout, tokens, feat, outp, bout);
}

// round 15
// speedup vs baseline: 1.1031x; 1.1031x over previous
#include <cuda_runtime.h>
#include <cuda_fp16.h>
#include <math.h>

// Problem constants
#define BATCH 16
#define DQ    768
#define NQ    1024
#define NT    64
#define DKV   384
#define NH    12
#define HD    64
#define NKV   (BATCH*NT)
#define DKV2  (2*DQ)

#define NEG_L2B_32 (-0.41524101186091903f)   // -log2(10000)/32

typedef unsigned short u16;
typedef unsigned int   u32;

// ---------------------------------------------------------------------------
// Scratch (device globals)
// ---------------------------------------------------------------------------
__device__ __align__(16) u16 g_qin_h[(size_t)BATCH*NQ*DQ];     // feat^T hi fp16
__device__ __align__(16) u16 g_k_h  [(size_t)BATCH*NH*NT*HD];  // rope'd K hi [b,h,t,hd]
__device__ __align__(16) u16 g_vT_h [(size_t)BATCH*NH*HD*NT];  // V^T hi [b,h,hd,t]
__device__ __align__(16) u16 g_o_h  [(size_t)BATCH*NQ*DQ];     // attn out hi [B,Nq,Dq]
__device__ __align__(16) u16 g_wq_h [DQ*DQ];                   // WqT hi
__device__ __align__(16) u16 g_wkv_h[DKV2*DKV];                // WkvT hi
__device__ __align__(16) u16 g_wo_h [DQ*DQ];                   // WoutT hi
__device__ __align__(16) u16 g_tok_h[NKV*DKV];                 // tokens hi
__device__ __align__(16) float2 g_cs[NQ*32];                   // (cos, sin)
__device__ u32 g_kvflag = 0;                                   // kv-CTA done count
__device__ u32 g_qdone[BATCH * 8 * 6];                         // per (bz, qtile, dqtile)

// ---------------------------------------------------------------------------
// Helpers (base-ISA only)
// ---------------------------------------------------------------------------
__device__ __forceinline__ u32 smem_u32(const void* p) {
    u32 a;
    asm("{ .reg .u64 t; cvta.to.shared.u64 t, %1; cvt.u32.u64 %0, t; }" : "=r"(a) : "l"(p));
    return a;
}
__device__ __forceinline__ u32 swz(u32 o) { return o ^ ((o >> 3) & 0x70); }

__device__ __forceinline__ void cpa16(u32 s, const void* g) {
    asm volatile("cp.async.cg.shared.global [%0], [%1], 16;" :: "r"(s), "l"(g) : "memory");
}
#define CP_COMMIT() asm volatile("cp.async.commit_group;" ::: "memory")
#define CP_WAIT(n)  asm volatile("cp.async.wait_group %0;" :: "n"(n) : "memory")

__device__ __forceinline__ void ldsm4(u32* r, u32 a) {
    asm volatile("ldmatrix.sync.aligned.m8n8.x4.shared.b16 {%0,%1,%2,%3}, [%4];"
                 : "=r"(r[0]), "=r"(r[1]), "=r"(r[2]), "=r"(r[3]) : "r"(a));
}
__device__ __forceinline__ void mma16816(float* c, const u32* a, const u32* b) {
    asm volatile(
        "mma.sync.aligned.m16n8k16.row.col.f32.f16.f16.f32 "
        "{%0,%1,%2,%3}, {%4,%5,%6,%7}, {%8,%9}, {%0,%1,%2,%3};"
        : "+f"(c[0]), "+f"(c[1]), "+f"(c[2]), "+f"(c[3])
        : "r"(a[0]), "r"(a[1]), "r"(a[2]), "r"(a[3]), "r"(b[0]), "r"(b[1]));
}

__device__ __forceinline__ u16 f16h(float v) {
    __half h = __float2half_rn(v);
    return *reinterpret_cast<u16*>(&h);
}
__device__ __forceinline__ u32 pack_h(float a, float b) {
    __half2 h = __float22half2_rn(make_float2(a, b));
    return *reinterpret_cast<u32*>(&h);
}

__device__ __forceinline__ void wait_ge(volatile u32* f, u32 target) {
    if (threadIdx.x == 0) {
        while (*f < target) __nanosleep(64);
        __threadfence();
    }
    __syncthreads();
}

// ---------------------------------------------------------------------------
// Fused prep kernel: weights T + tokens + rope table + feat transpose + flags
// ---------------------------------------------------------------------------
__device__ __forceinline__ void convT_tile(const float* __restrict__ in,
                                           u16* __restrict__ oh,
                                           int R, int C, int bx, int by,
                                           float (*t)[33])
{
    int txx = threadIdx.x & 31, tyy = threadIdx.x >> 5;
    int x = bx * 32 + txx;
    int y0 = by * 32 + tyy;
    #pragma unroll
    for (int i = 0; i < 32; i += 8)
        t[tyy + i][txx] = in[(size_t)(y0 + i) * C + x];
    __syncthreads();
    int orow0 = bx * 32 + tyy;
    int ocol  = by * 32 + txx;
    #pragma unroll
    for (int i = 0; i < 32; i += 8)
        oh[(size_t)(orow0 + i) * R + ocol] = f16h(t[txx][tyy + i]);
}

__device__ __forceinline__ void conv_feat64(const float* __restrict__ in,
                                            u16* __restrict__ out,
                                            int bd, int bn, float (*t)[65])
{
    const int tid = threadIdx.x;
    #pragma unroll
    for (int it = 0; it < 4; it++) {
        int idx = it * 256 + tid;
        int r = idx >> 4, c4 = idx & 15;
        float4 v = *(const float4*)(in + (size_t)(bd * 64 + r) * NQ + bn * 64 + c4 * 4);
        t[r][c4 * 4 + 0] = v.x; t[r][c4 * 4 + 1] = v.y;
        t[r][c4 * 4 + 2] = v.z; t[r][c4 * 4 + 3] = v.w;
    }
    __syncthreads();
    #pragma unroll
    for (int it = 0; it < 2; it++) {
        int idx = it * 256 + tid;
        int r = idx >> 3, c = idx & 7;
        u32 w0 = pack_h(t[c * 8 + 0][r], t[c * 8 + 1][r]);
        u32 w1 = pack_h(t[c * 8 + 2][r], t[c * 8 + 3][r]);
        u32 w2 = pack_h(t[c * 8 + 4][r], t[c * 8 + 5][r]);
        u32 w3 = pack_h(t[c * 8 + 6][r], t[c * 8 + 7][r]);
        *(uint4*)(out + (size_t)(bn * 64 + r) * DQ + bd * 64 + c * 8) =
            make_uint4(w0, w1, w2, w3);
    }
}

__global__ void __launch_bounds__(256)
conv_all(const float* __restrict__ Wq, const float* __restrict__ Wkv,
         const float* __restrict__ Wout, const float* __restrict__ tok,
         const float* __restrict__ feat)
{
    __shared__ float tbuf[64 * 65];
    int bid = blockIdx.x;
    if (bid < 576) {
        convT_tile(Wq, g_wq_h, DQ, DQ, bid % 24, bid / 24, (float(*)[33])tbuf);
    } else if (bid < 1152) {
        int i = bid - 576;
        convT_tile(Wkv, g_wkv_h, DKV, DKV2, i % 48, i / 48, (float(*)[33])tbuf);
    } else if (bid < 1728) {
        int i = bid - 1152;
        convT_tile(Wout, g_wo_h, DQ, DQ, i % 24, i / 24, (float(*)[33])tbuf);
    } else if (bid < 2112) {
        int base = (bid - 1728) * 1024 + threadIdx.x * 4;
        float4 v = *(const float4*)(tok + base);
        *(u32*)&g_tok_h[base]     = pack_h(v.x, v.y);
        *(u32*)&g_tok_h[base + 2] = pack_h(v.z, v.w);
    } else if (bid < 2240) {
        if (bid == 2112) {
            if (threadIdx.x == 0) g_kvflag = 0;
            for (int i = threadIdx.x; i < BATCH * 8 * 6; i += 256) g_qdone[i] = 0;
        }
        int idx = (bid - 2112) * 256 + threadIdx.x;
        int pos = idx >> 5, i = idx & 31;
        float inv = exp2f((float)i * NEG_L2B_32);
        float sn, cs;
        sincosf((float)pos * inv, &sn, &cs);
        g_cs[idx] = make_float2(cs, sn);
    } else {
        int i = bid - 2240;            // 3072 blocks: 16 z x 12 bd x 16 bn
        int z = i / 192;
        int rem = i % 192;
        int bd = rem >> 4;
        int bn = rem & 15;
        conv_feat64(feat + (size_t)z * DQ * NQ, g_qin_h + (size_t)z * NQ * DQ,
                    bd, bn, (float(*)[65])tbuf);
    }
}

// ---------------------------------------------------------------------------
// Shared GEMM config
// ---------------------------------------------------------------------------
#define BK 64
#define STG 32768
#define AH_O 0
#define BH_O 16384
#define GSMEM (3*STG)
#define QOFF 0
#define KOFF 32768
#define VOFF 49152

#define GEMM_PREAMBLE                                                            \
    extern __shared__ char smdyn[];                                              \
    const u32 sbase = smem_u32(smdyn);                                           \
    const int tid  = threadIdx.x;                                                \
    const int lane = tid & 31;                                                   \
    const int wid  = tid >> 5;                                                   \
    const int wm   = (wid & 3) * 32;                                             \
    const int wn   = (wid >> 2) * 64;

#define LOAD_STAGE(kt, slot) do {                                                \
    u32 so_ = sbase + (u32)(slot) * STG;                                         \
    int k0_ = (kt) * BK;                                                         \
    _Pragma("unroll")                                                            \
    for (int i_ = 0; i_ < 4; i_++) {                                             \
        int chunk_ = i_ * 256 + tid;                                             \
        int row_ = chunk_ >> 3, c_ = chunk_ & 7;                                 \
        u32 off_ = swz((u32)(row_ * 128 + c_ * 16));                             \
        size_t ga_ = (size_t)(m0 + row_) * K + k0_ + c_ * 8;                     \
        size_t gb_ = (size_t)(n0 + row_) * K + k0_ + c_ * 8;                     \
        cpa16(so_ + AH_O + off_, Ahb + ga_);                                     \
        cpa16(so_ + BH_O + off_, Bhb + gb_);                                     \
    }                                                                            \
} while (0)

#define LOAD_FRAGS(buf, sa, ks) do {                                             \
    _Pragma("unroll")                                                            \
    for (int mi_ = 0; mi_ < 2; mi_++) {                                          \
        int row_ = wm + mi_ * 16 + (lane & 15);                                  \
        int chunk_ = 2 * (ks) + (lane >> 4);                                     \
        ldsm4(ahf[buf][mi_], (sa) + AH_O + swz((u32)(row_ * 128 + chunk_ * 16))); \
    }                                                                            \
    _Pragma("unroll")                                                            \
    for (int jj_ = 0; jj_ < 4; jj_++) {                                          \
        int g_ = lane >> 3;                                                      \
        int row_ = wn + (2 * jj_ + (g_ >> 1)) * 8 + (lane & 7);                  \
        int chunk_ = 2 * (ks) + (g_ & 1);                                        \
        u32 t_[4];                                                               \
        ldsm4(t_, (sa) + BH_O + swz((u32)(row_ * 128 + chunk_ * 16)));           \
        bhf[buf][2*jj_][0] = t_[0]; bhf[buf][2*jj_][1] = t_[1];                  \
        bhf[buf][2*jj_+1][0] = t_[2]; bhf[buf][2*jj_+1][1] = t_[3];              \
    }                                                                            \
} while (0)

// mainloop with optional incremental producer waits (qflags != nullptr):
// before prefetching k-chunk kt, require g_qdone flag for dq-tile kt>>1.
#define GEMM_MAINLOOP                                                            \
    float acc[2][8][4];                                                          \
    _Pragma("unroll")                                                            \
    for (int i = 0; i < 2; i++)                                                  \
        _Pragma("unroll")                                                        \
        for (int j = 0; j < 8; j++)                                              \
            _Pragma("unroll")                                                    \
            for (int p = 0; p < 4; p++) acc[i][j][p] = 0.f;                      \
    const int KT = K / BK;                                                       \
    if (qflags) wait_ge(qflags, 1);                                              \
    LOAD_STAGE(0, 0);                                                            \
    CP_COMMIT();                                                                 \
    if (KT > 1) { LOAD_STAGE(1, 1); CP_COMMIT(); }                               \
    u32 ahf[2][2][4], bhf[2][8][2];                                              \
    int slot = 0;                                                                \
    for (int kt = 0; kt < KT; kt++) {                                            \
        if (kt + 1 < KT) CP_WAIT(1); else CP_WAIT(0);                            \
        __syncthreads();                                                         \
        if (kt + 2 < KT) {                                                       \
            if (qflags && (((kt + 2) & 1) == 0))                                 \
                wait_ge(qflags + ((kt + 2) >> 1), 1);                            \
            int ns = slot + 2; if (ns >= 3) ns -= 3;                             \
            LOAD_STAGE(kt + 2, ns);                                              \
            CP_COMMIT();                                                         \
        }                                                                        \
        const u32 sa = sbase + (u32)slot * STG;                                  \
        LOAD_FRAGS(0, sa, 0);                                                    \
        _Pragma("unroll")                                                        \
        for (int ks = 0; ks < 4; ks++) {                                         \
            const int cur = ks & 1;                                              \
            if (ks < 3) LOAD_FRAGS(!cur ? 1 : 0, sa, ks + 1);                    \
            _Pragma("unroll")                                                    \
            for (int mi = 0; mi < 2; mi++)                                       \
                _Pragma("unroll")                                                \
                for (int ni = 0; ni < 8; ni++)                                   \
                    mma16816(acc[mi][ni], ahf[cur][mi], bhf[cur][ni]);           \
        }                                                                        \
        slot++; if (slot >= 3) slot = 0;                                         \
    }

// ---------------------------------------------------------------------------
// Fused kernel: kv-proj (96) -> q-proj+attention (768) -> out-proj (768)
// ---------------------------------------------------------------------------
__global__ void __launch_bounds__(256, 2)
gemm_fused(const u16* __restrict__ Qin, const u16* __restrict__ Wq,
           const u16* __restrict__ Tok, const u16* __restrict__ Wkv,
           const u16* __restrict__ Wo,
           float* __restrict__ C, const float* __restrict__ Feat,
           const float* __restrict__ Bias)
{
    GEMM_PREAMBLE
    const int gbid = blockIdx.x;
    const int cls = (gbid < 96) ? 0 : (gbid < 864 ? 1 : 2);
    int m0, n0, bz, K;
    const u16 *Ahb, *Bhb;
    u32* qflags = nullptr;
    if (cls == 0) {
        n0 = (gbid % 12) * 128;
        m0 = (gbid / 12) * 128;
        bz = 0;
        Ahb = Tok; Bhb = Wkv; K = DKV;
    } else if (cls == 1) {
        int i = gbid - 96;
        bz = i / 48;
        int rem = i % 48;
        m0 = (rem / 6) * 128;          // q rows
        n0 = (rem % 6) * 128;          // dq cols (2 heads)
        Ahb = Qin + (size_t)bz * NQ * DQ; Bhb = Wq; K = DQ;
    } else {
        int i = gbid - 864;
        bz = i / 48;
        int rem = i % 48;
        m0 = (rem % 6) * 128;          // d rows
        n0 = (rem / 6) * 128;          // q cols
        Ahb = Wo; Bhb = g_o_h + (size_t)bz * NQ * DQ; K = DQ;
        qflags = &g_qdone[(bz * 8 + (n0 >> 7)) * 6];
    }

    GEMM_MAINLOOP

    if (cls == 0) {
        // ---- kv epilogue: RoPE K / transpose V, publish ----
        if (n0 + wn < DQ) {
            #pragma unroll
            for (int mi = 0; mi < 2; mi++)
                #pragma unroll
                for (int ni = 0; ni < 4; ni++)
                    #pragma unroll
                    for (int half = 0; half < 2; half++) {
                        int m = m0 + wm + mi * 16 + (lane >> 2) + half * 8;
                        int bb = m >> 6, t = m & 63;
                        int n = n0 + wn + ni * 8 + (lane & 3) * 2;
                        int h = n >> 6;
                        int i0 = n & 63;
                        float2 cs0 = g_cs[t * 32 + i0];
                        float2 cs1 = g_cs[t * 32 + i0 + 1];
                        float x1a = acc[mi][ni][half*2],   x2a = acc[mi][ni+4][half*2];
                        float x1b = acc[mi][ni][half*2+1], x2b = acc[mi][ni+4][half*2+1];
                        float y1a = x1a * cs0.x - x2a * cs0.y;
                        float y2a = x2a * cs0.x + x1a * cs0.y;
                        float y1b = x1b * cs1.x - x2b * cs1.y;
                        float y2b = x2b * cs1.x + x1b * cs1.y;
                        size_t base = (((size_t)bb * NH + h) * NT + t) * HD;
                        *(u32*)&g_k_h[base + i0]      = pack_h(y1a, y1b);
                        *(u32*)&g_k_h[base + i0 + 32] = pack_h(y2a, y2b);
                    }
        } else {
            #pragma unroll
            for (int mi = 0; mi < 2; mi++)
                #pragma unroll
                for (int ni = 0; ni < 8; ni++)
                    #pragma unroll
                    for (int p = 0; p < 4; p++) {
                        int m = m0 + wm + mi * 16 + (lane >> 2) + (p >> 1) * 8;
                        int bb = m >> 6, t = m & 63;
                        int n = n0 + wn + ni * 8 + (lane & 3) * 2 + (p & 1);
                        int h = (n - DQ) >> 6;
                        int hd = n & 63;
                        size_t o = (((size_t)bb * NH + h) * HD + hd) * NT + t;
                        g_vT_h[o] = f16h(acc[mi][ni][p]);
                    }
        }
        __threadfence();
        __syncthreads();
        if (tid == 0) atomicAdd(&g_kvflag, 1u);
        return;
    }

    if (cls == 2) {
        // ---- out epilogue ----
        #pragma unroll
        for (int mi = 0; mi < 2; mi++)
            #pragma unroll
            for (int ni = 0; ni < 8; ni++) {
                int m = m0 + wm + mi * 16 + (lane >> 2);
                int n = n0 + wn + ni * 8 + (lane & 3) * 2;
                const float* c = acc[mi][ni];
                size_t a0 = ((size_t)bz * DQ + m) * NQ + n;
                size_t a1 = ((size_t)bz * DQ + m + 8) * NQ + n;
                float b0 = Bias[m], b1 = Bias[m + 8];
                float2 f0 = *(const float2*)&Feat[a0];
                float2 f1 = *(const float2*)&Feat[a1];
                *(float2*)&C[a0] = make_float2(c[0] + f0.x + b0, c[1] + f0.y + b0);
                *(float2*)&C[a1] = make_float2(c[2] + f1.x + b1, c[3] + f1.y + b1);
            }
        return;
    }

    // ---- q epilogue: RoPE -> smem, wait kv, attention, publish ----
    __syncthreads();

    const int hh_w = wid >> 2;
    const u32 qbase = sbase + QOFF + (u32)hh_w * 16384;
    #pragma unroll
    for (int mi = 0; mi < 2; mi++)
        #pragma unroll
        for (int ni = 0; ni < 4; ni++)
            #pragma unroll
            for (int half = 0; half < 2; half++) {
                int m_loc = wm + mi * 16 + (lane >> 2) + half * 8;
                int m = m0 + m_loc;
                int i0 = ni * 8 + (lane & 3) * 2;
                float2 cs0 = g_cs[m * 32 + i0];
                float2 cs1 = g_cs[m * 32 + i0 + 1];
                float x1a = acc[mi][ni][half*2],   x2a = acc[mi][ni+4][half*2];
                float x1b = acc[mi][ni][half*2+1], x2b = acc[mi][ni+4][half*2+1];
                float y1a = x1a * cs0.x - x2a * cs0.y;
                float y2a = x2a * cs0.x + x1a * cs0.y;
                float y1b = x1b * cs1.x - x2b * cs1.y;
                float y2b = x2b * cs1.x + x1b * cs1.y;
                asm volatile("st.shared.u32 [%0], %1;" ::
                    "r"(qbase + swz((u32)(m_loc * 128 + i0 * 2))), "r"(pack_h(y1a, y1b)));
                asm volatile("st.shared.u32 [%0], %1;" ::
                    "r"(qbase + swz((u32)(m_loc * 128 + (i0 + 32) * 2))), "r"(pack_h(y2a, y2b)));
            }

    wait_ge(&g_kvflag, 96);

    const int hbase = n0 >> 6;
    {
        size_t kvb = ((size_t)bz * NH + hbase) * (NT * HD);
        #pragma unroll
        for (int i = 0; i < 4; i++) {
            int c = i * 256 + tid;
            int hh = c >> 9;
            int r  = (c >> 3) & 63;
            int cc = c & 7;
            u32 off = (u32)hh * 8192 + swz((u32)(r * 128 + cc * 16));
            cpa16(sbase + KOFF + off, g_k_h  + kvb + (size_t)hh * (NT*HD) + r * HD + cc * 8);
            cpa16(sbase + VOFF + off, g_vT_h + kvb + (size_t)hh * (NT*HD) + r * HD + cc * 8);
        }
        CP_COMMIT();
        CP_WAIT(0);
        __syncthreads();
    }

    const u32 kbase = sbase + KOFF + (u32)hh_w * 8192;
    const u32 vbase = sbase + VOFF + (u32)hh_w * 8192;
    const int qw = (wid & 3) * 32;

    float s[2][8][4];
    #pragma unroll
    for (int i = 0; i < 2; i++)
        #pragma unroll
        for (int j = 0; j < 8; j++)
            #pragma unroll
            for (int p = 0; p < 4; p++) s[i][j][p] = 0.f;

    #pragma unroll
    for (int ks = 0; ks < 4; ks++) {
        u32 aq[2][4], bk[8][2];
        #pragma unroll
        for (int mi = 0; mi < 2; mi++) {
            int row = qw + mi * 16 + (lane & 15);
            int chunk = 2 * ks + (lane >> 4);
            ldsm4(aq[mi], qbase + swz((u32)(row * 128 + chunk * 16)));
        }
        #pragma unroll
        for (int jj = 0; jj < 4; jj++) {
            int g = lane >> 3;
            int row = (2 * jj + (g >> 1)) * 8 + (lane & 7);
            int chunk = 2 * ks + (g & 1);
            u32 t[4];
            ldsm4(t, kbase + swz((u32)(row * 128 + chunk * 16)));
            bk[2*jj][0] = t[0]; bk[2*jj][1] = t[1];
            bk[2*jj+1][0] = t[2]; bk[2*jj+1][1] = t[3];
        }
        #pragma unroll
        for (int mi = 0; mi < 2; mi++)
            #pragma unroll
            for (int ni = 0; ni < 8; ni++)
                mma16816(s[mi][ni], aq[mi], bk[ni]);
    }

    // softmax (scale 1/8)
    #pragma unroll
    for (int mi = 0; mi < 2; mi++) {
        float mx0 = -1e30f, mx1 = -1e30f;
        #pragma unroll
        for (int ni = 0; ni < 8; ni++) {
            #pragma unroll
            for (int p = 0; p < 4; p++) s[mi][ni][p] *= 0.125f;
            mx0 = fmaxf(mx0, fmaxf(s[mi][ni][0], s[mi][ni][1]));
            mx1 = fmaxf(mx1, fmaxf(s[mi][ni][2], s[mi][ni][3]));
        }
        mx0 = fmaxf(mx0, __shfl_xor_sync(0xffffffffu, mx0, 1));
        mx0 = fmaxf(mx0, __shfl_xor_sync(0xffffffffu, mx0, 2));
        mx1 = fmaxf(mx1, __shfl_xor_sync(0xffffffffu, mx1, 1));
        mx1 = fmaxf(mx1, __shfl_xor_sync(0xffffffffu, mx1, 2));
        float sm0 = 0.f, sm1 = 0.f;
        #pragma unroll
        for (int ni = 0; ni < 8; ni++) {
            s[mi][ni][0] = __expf(s[mi][ni][0] - mx0);
            s[mi][ni][1] = __expf(s[mi][ni][1] - mx0);
            s[mi][ni][2] = __expf(s[mi][ni][2] - mx1);
            s[mi][ni][3] = __expf(s[mi][ni][3] - mx1);
            sm0 += s[mi][ni][0] + s[mi][ni][1];
            sm1 += s[mi][ni][2] + s[mi][ni][3];
        }
        sm0 += __shfl_xor_sync(0xffffffffu, sm0, 1);
        sm0 += __shfl_xor_sync(0xffffffffu, sm0, 2);
        sm1 += __shfl_xor_sync(0xffffffffu, sm1, 1);
        sm1 += __shfl_xor_sync(0xffffffffu, sm1, 2);
        float i0 = 1.f / sm0, i1 = 1.f / sm1;
        #pragma unroll
        for (int ni = 0; ni < 8; ni++) {
            s[mi][ni][0] *= i0; s[mi][ni][1] *= i0;
            s[mi][ni][2] *= i1; s[mi][ni][3] *= i1;
        }
    }

    // O = P V
    float o[2][8][4];
    #pragma unroll
    for (int i = 0; i < 2; i++)
        #pragma unroll
        for (int j = 0; j < 8; j++)
            #pragma unroll
            for (int p = 0; p < 4; p++) o[i][j][p] = 0.f;

    #pragma unroll
    for (int kc = 0; kc < 4; kc++) {
        u32 pah[2][4], bv[8][2];
        #pragma unroll
        for (int mi = 0; mi < 2; mi++) {
            pah[mi][0] = pack_h(s[mi][2*kc][0],   s[mi][2*kc][1]);
            pah[mi][1] = pack_h(s[mi][2*kc][2],   s[mi][2*kc][3]);
            pah[mi][2] = pack_h(s[mi][2*kc+1][0], s[mi][2*kc+1][1]);
            pah[mi][3] = pack_h(s[mi][2*kc+1][2], s[mi][2*kc+1][3]);
        }
        #pragma unroll
        for (int jj = 0; jj < 4; jj++) {
            int g = lane >> 3;
            int row = (2 * jj + (g >> 1)) * 8 + (lane & 7);
            int chunk = 2 * kc + (g & 1);
            u32 t[4];
            ldsm4(t, vbase + swz((u32)(row * 128 + chunk * 16)));
            bv[2*jj][0] = t[0]; bv[2*jj][1] = t[1];
            bv[2*jj+1][0] = t[2]; bv[2*jj+1][1] = t[3];
        }
        #pragma unroll
        for (int mi = 0; mi < 2; mi++)
            #pragma unroll
            for (int ni = 0; ni < 8; ni++)
                mma16816(o[mi][ni], pah[mi], bv[ni]);
    }

    // store O hi fp16 at [B,Nq,Dq], then publish fine-grained flag
    #pragma unroll
    for (int mi = 0; mi < 2; mi++)
        #pragma unroll
        for (int ni = 0; ni < 8; ni++) {
            int q = m0 + qw + mi * 16 + (lane >> 2);
            int col = n0 + hh_w * 64 + ni * 8 + (lane & 3) * 2;
            size_t a0 = ((size_t)(bz * NQ + q)) * DQ + col;
            size_t a1 = ((size_t)(bz * NQ + q + 8)) * DQ + col;
            *(u32*)&g_o_h[a0] = pack_h(o[mi][ni][0], o[mi][ni][1]);
            *(u32*)&g_o_h[a1] = pack_h(o[mi][ni][2], o[mi][ni][3]);
        }
    __threadfence();
    __syncthreads();
    if (tid == 0) atomicAdd(&g_qdone[(bz * 8 + (m0 >> 7)) * 6 + (n0 >> 7)], 1u);
}

// ---------------------------------------------------------------------------
// Launch
// ---------------------------------------------------------------------------
extern "C" void kernel_launch(void* const* d_in, const int* in_sizes, int n_in,
                              void* d_out, int out_size)
{
    (void)in_sizes; (void)n_in; (void)out_size;
    const float* feat   = (const float*)d_in[0];
    const float* tokens = (const float*)d_in[1];
    const float* Wq     = (const float*)d_in[2];
    const float* Wkv    = (const float*)d_in[3];
    const float* Wout   = (const float*)d_in[4];
    const float* bout   = (const float*)d_in[5];
    float* outp = (float*)d_out;

    u16 *pqih, *pwqh, *pwkh, *pwoh, *pth;
    cudaGetSymbolAddress((void**)&pqih, g_qin_h);
    cudaGetSymbolAddress((void**)&pwqh, g_wq_h);
    cudaGetSymbolAddress((void**)&pwkh, g_wkv_h);
    cudaGetSymbolAddress((void**)&pwoh, g_wo_h);
    cudaGetSymbolAddress((void**)&pth,  g_tok_h);

    cudaFuncSetAttribute(gemm_fused, cudaFuncAttributeMaxDynamicSharedMemorySize, GSMEM);

    // preprocessing at high occupancy (weights, tokens, rope, feat, flag resets)
    conv_all<<<2240 + 3072, 256>>>(Wq, Wkv, Wout, tokens, feat);

    // fused: kv-proj -> q-proj + RoPE + attention -> out-proj (incremental deps)
    gemm_fused<<<96 + 768 + 768, 256, GSMEM>>>(
        pqih, pwqh, pth, pwkh, pwoh, outp, feat, bout);
}

// round 16
// speedup vs baseline: 1.2430x; 1.1269x over previous
#include <cuda_runtime.h>
#include <cuda_fp16.h>
#include <math.h>

// Problem constants
#define BATCH 16
#define DQ    768
#define NQ    1024
#define NT    64
#define DKV   384
#define NH    12
#define HD    64
#define NKV   (BATCH*NT)
#define DKV2  (2*DQ)

#define NEG_L2B_32 (-0.41524101186091903f)   // -log2(10000)/32

typedef unsigned short u16;
typedef unsigned int   u32;

// ---------------------------------------------------------------------------
// Scratch (device globals)
// ---------------------------------------------------------------------------
__device__ __align__(16) u16 g_qin_h[(size_t)BATCH*NQ*DQ];     // feat^T hi fp16
__device__ __align__(16) u16 g_k_h  [(size_t)BATCH*NH*NT*HD];  // rope'd K hi [b,h,t,hd]
__device__ __align__(16) u16 g_vT_h [(size_t)BATCH*NH*HD*NT];  // V^T hi [b,h,hd,t]
__device__ __align__(16) u16 g_o_h  [(size_t)BATCH*NQ*DQ];     // attn out hi [B,Nq,Dq]
__device__ __align__(16) u16 g_wq_h [DQ*DQ];                   // WqT hi
__device__ __align__(16) u16 g_wkv_h[DKV2*DKV];                // WkvT hi
__device__ __align__(16) u16 g_wo_h [DQ*DQ];                   // WoutT hi
__device__ __align__(16) u16 g_tok_h[NKV*DKV];                 // tokens hi
__device__ __align__(16) float2 g_cs[NQ*32];                   // (cos, sin)
__device__ u32 g_kvflag = 0;                                   // kv-CTA done count
__device__ u32 g_qdone[BATCH * 8];                             // per (bz, qtile) done count

// ---------------------------------------------------------------------------
// Helpers (base-ISA only)
// ---------------------------------------------------------------------------
__device__ __forceinline__ u32 smem_u32(const void* p) {
    u32 a;
    asm("{ .reg .u64 t; cvta.to.shared.u64 t, %1; cvt.u32.u64 %0, t; }" : "=r"(a) : "l"(p));
    return a;
}
__device__ __forceinline__ u32 swz(u32 o) { return o ^ ((o >> 3) & 0x70); }

__device__ __forceinline__ void cpa16(u32 s, const void* g) {
    asm volatile("cp.async.cg.shared.global [%0], [%1], 16;" :: "r"(s), "l"(g) : "memory");
}
#define CP_COMMIT() asm volatile("cp.async.commit_group;" ::: "memory")
#define CP_WAIT(n)  asm volatile("cp.async.wait_group %0;" :: "n"(n) : "memory")

__device__ __forceinline__ void ldsm4(u32* r, u32 a) {
    asm volatile("ldmatrix.sync.aligned.m8n8.x4.shared.b16 {%0,%1,%2,%3}, [%4];"
                 : "=r"(r[0]), "=r"(r[1]), "=r"(r[2]), "=r"(r[3]) : "r"(a));
}
__device__ __forceinline__ void mma16816(float* c, const u32* a, const u32* b) {
    asm volatile(
        "mma.sync.aligned.m16n8k16.row.col.f32.f16.f16.f32 "
        "{%0,%1,%2,%3}, {%4,%5,%6,%7}, {%8,%9}, {%0,%1,%2,%3};"
        : "+f"(c[0]), "+f"(c[1]), "+f"(c[2]), "+f"(c[3])
        : "r"(a[0]), "r"(a[1]), "r"(a[2]), "r"(a[3]), "r"(b[0]), "r"(b[1]));
}

__device__ __forceinline__ u16 f16h(float v) {
    __half h = __float2half_rn(v);
    return *reinterpret_cast<u16*>(&h);
}
__device__ __forceinline__ u32 pack_h(float a, float b) {
    __half2 h = __float22half2_rn(make_float2(a, b));
    return *reinterpret_cast<u32*>(&h);
}

// ---------------------------------------------------------------------------
// Prep kernel: vectorized 64x64 transposes (weights + feat), tokens, rope, flags
// Block ranges: [0,144) Wq | [144,288) Wkv | [288,432) Wout |
//               [432,816) tokens | [816,944) rope+flags | [944,944+3072) feat
// ---------------------------------------------------------------------------
__device__ __forceinline__ void conv_T64(const float* __restrict__ in,
                                         u16* __restrict__ out,
                                         int ld_in, int ld_out,
                                         int bd, int bn, float (*t)[65])
{
    const int tid = threadIdx.x;
    #pragma unroll
    for (int it = 0; it < 4; it++) {
        int idx = it * 256 + tid;
        int r = idx >> 4, c4 = idx & 15;
        float4 v = *(const float4*)(in + (size_t)(bd * 64 + r) * ld_in + bn * 64 + c4 * 4);
        t[r][c4 * 4 + 0] = v.x; t[r][c4 * 4 + 1] = v.y;
        t[r][c4 * 4 + 2] = v.z; t[r][c4 * 4 + 3] = v.w;
    }
    __syncthreads();
    #pragma unroll
    for (int it = 0; it < 2; it++) {
        int idx = it * 256 + tid;
        int r = idx >> 3, c = idx & 7;          // r = out row (in col), c = 8-chunk
        u32 w0 = pack_h(t[c * 8 + 0][r], t[c * 8 + 1][r]);
        u32 w1 = pack_h(t[c * 8 + 2][r], t[c * 8 + 3][r]);
        u32 w2 = pack_h(t[c * 8 + 4][r], t[c * 8 + 5][r]);
        u32 w3 = pack_h(t[c * 8 + 6][r], t[c * 8 + 7][r]);
        *(uint4*)(out + (size_t)(bn * 64 + r) * ld_out + bd * 64 + c * 8) =
            make_uint4(w0, w1, w2, w3);
    }
}

__global__ void __launch_bounds__(256)
conv_all(const float* __restrict__ Wq, const float* __restrict__ Wkv,
         const float* __restrict__ Wout, const float* __restrict__ tok,
         const float* __restrict__ feat)
{
    __shared__ float tbuf[64 * 65];
    int bid = blockIdx.x;
    if (bid < 144) {
        conv_T64(Wq, g_wq_h, DQ, DQ, bid / 12, bid % 12, (float(*)[65])tbuf);
    } else if (bid < 288) {
        int i = bid - 144;
        conv_T64(Wkv, g_wkv_h, DKV2, DKV, i / 24, i % 24, (float(*)[65])tbuf);
    } else if (bid < 432) {
        int i = bid - 288;
        conv_T64(Wout, g_wo_h, DQ, DQ, i / 12, i % 12, (float(*)[65])tbuf);
    } else if (bid < 816) {
        int base = (bid - 432) * 1024 + threadIdx.x * 4;
        float4 v = *(const float4*)(tok + base);
        *(u32*)&g_tok_h[base]     = pack_h(v.x, v.y);
        *(u32*)&g_tok_h[base + 2] = pack_h(v.z, v.w);
    } else if (bid < 944) {
        if (bid == 816) {
            if (threadIdx.x == 0) g_kvflag = 0;
            if (threadIdx.x < BATCH * 8) g_qdone[threadIdx.x] = 0;
        }
        int idx = (bid - 816) * 256 + threadIdx.x;
        int pos = idx >> 5, i = idx & 31;
        float inv = exp2f((float)i * NEG_L2B_32);
        float sn, cs;
        sincosf((float)pos * inv, &sn, &cs);
        g_cs[idx] = make_float2(cs, sn);
    } else {
        int i = bid - 944;             // 3072 blocks: 16 z x 12 bd x 16 bn
        int z = i / 192;
        int rem = i % 192;
        int bd = rem >> 4;
        int bn = rem & 15;
        conv_T64(feat + (size_t)z * DQ * NQ, g_qin_h + (size_t)z * NQ * DQ,
                 NQ, DQ, bd, bn, (float(*)[65])tbuf);
    }
}

// ---------------------------------------------------------------------------
// Shared GEMM config
// ---------------------------------------------------------------------------
#define BK 64
#define STG 32768
#define AH_O 0
#define BH_O 16384
#define GSMEM (3*STG)
#define QOFF 0
#define KOFF 32768
#define VOFF 49152

#define GEMM_PREAMBLE                                                            \
    extern __shared__ char smdyn[];                                              \
    const u32 sbase = smem_u32(smdyn);                                           \
    const int tid  = threadIdx.x;                                                \
    const int lane = tid & 31;                                                   \
    const int wid  = tid >> 5;                                                   \
    const int wm   = (wid & 3) * 32;                                             \
    const int wn   = (wid >> 2) * 64;

#define LOAD_STAGE(kt, slot) do {                                                \
    u32 so_ = sbase + (u32)(slot) * STG;                                         \
    int k0_ = (kt) * BK;                                                         \
    _Pragma("unroll")                                                            \
    for (int i_ = 0; i_ < 4; i_++) {                                             \
        int chunk_ = i_ * 256 + tid;                                             \
        int row_ = chunk_ >> 3, c_ = chunk_ & 7;                                 \
        u32 off_ = swz((u32)(row_ * 128 + c_ * 16));                             \
        size_t ga_ = (size_t)(m0 + row_) * K + k0_ + c_ * 8;                     \
        size_t gb_ = (size_t)(n0 + row_) * K + k0_ + c_ * 8;                     \
        cpa16(so_ + AH_O + off_, Ahb + ga_);                                     \
        cpa16(so_ + BH_O + off_, Bhb + gb_);                                     \
    }                                                                            \
} while (0)

#define LOAD_FRAGS(buf, sa, ks) do {                                             \
    _Pragma("unroll")                                                            \
    for (int mi_ = 0; mi_ < 2; mi_++) {                                          \
        int row_ = wm + mi_ * 16 + (lane & 15);                                  \
        int chunk_ = 2 * (ks) + (lane >> 4);                                     \
        ldsm4(ahf[buf][mi_], (sa) + AH_O + swz((u32)(row_ * 128 + chunk_ * 16))); \
    }                                                                            \
    _Pragma("unroll")                                                            \
    for (int jj_ = 0; jj_ < 4; jj_++) {                                          \
        int g_ = lane >> 3;                                                      \
        int row_ = wn + (2 * jj_ + (g_ >> 1)) * 8 + (lane & 7);                  \
        int chunk_ = 2 * (ks) + (g_ & 1);                                        \
        u32 t_[4];                                                               \
        ldsm4(t_, (sa) + BH_O + swz((u32)(row_ * 128 + chunk_ * 16)));           \
        bhf[buf][2*jj_][0] = t_[0]; bhf[buf][2*jj_][1] = t_[1];                  \
        bhf[buf][2*jj_+1][0] = t_[2]; bhf[buf][2*jj_+1][1] = t_[3];              \
    }                                                                            \
} while (0)

#define GEMM_MAINLOOP                                                            \
    float acc[2][8][4];                                                          \
    _Pragma("unroll")                                                            \
    for (int i = 0; i < 2; i++)                                                  \
        _Pragma("unroll")                                                        \
        for (int j = 0; j < 8; j++)                                              \
            _Pragma("unroll")                                                    \
            for (int p = 0; p < 4; p++) acc[i][j][p] = 0.f;                      \
    const int KT = K / BK;                                                       \
    LOAD_STAGE(0, 0);                                                            \
    CP_COMMIT();                                                                 \
    if (KT > 1) { LOAD_STAGE(1, 1); CP_COMMIT(); }                               \
    u32 ahf[2][2][4], bhf[2][8][2];                                              \
    int slot = 0;                                                                \
    for (int kt = 0; kt < KT; kt++) {                                            \
        if (kt + 1 < KT) CP_WAIT(1); else CP_WAIT(0);                            \
        __syncthreads();                                                         \
        if (kt + 2 < KT) {                                                       \
            int ns = slot + 2; if (ns >= 3) ns -= 3;                             \
            LOAD_STAGE(kt + 2, ns);                                              \
            CP_COMMIT();                                                         \
        }                                                                        \
        const u32 sa = sbase + (u32)slot * STG;                                  \
        LOAD_FRAGS(0, sa, 0);                                                    \
        _Pragma("unroll")                                                        \
        for (int ks = 0; ks < 4; ks++) {                                         \
            const int cur = ks & 1;                                              \
            if (ks < 3) LOAD_FRAGS(!cur ? 1 : 0, sa, ks + 1);                    \
            _Pragma("unroll")                                                    \
            for (int mi = 0; mi < 2; mi++)                                       \
                _Pragma("unroll")                                                \
                for (int ni = 0; ni < 8; ni++)                                   \
                    mma16816(acc[mi][ni], ahf[cur][mi], bhf[cur][ni]);           \
        }                                                                        \
        slot++; if (slot >= 3) slot = 0;                                         \
    }

// ---------------------------------------------------------------------------
// Fused kernel: kv-proj (96) -> q-proj+attention (768) -> out-proj (768)
// 1D grid, dispatch order gives producer-before-consumer. (R13-proven)
// ---------------------------------------------------------------------------
__global__ void __launch_bounds__(256, 2)
gemm_fused(const u16* __restrict__ Qin, const u16* __restrict__ Wq,
           const u16* __restrict__ Tok, const u16* __restrict__ Wkv,
           const u16* __restrict__ Wo,
           float* __restrict__ C, const float* __restrict__ Feat,
           const float* __restrict__ Bias)
{
    GEMM_PREAMBLE
    const int gbid = blockIdx.x;
    const int cls = (gbid < 96) ? 0 : (gbid < 864 ? 1 : 2);
    int m0, n0, bz, K;
    const u16 *Ahb, *Bhb;
    if (cls == 0) {
        n0 = (gbid % 12) * 128;
        m0 = (gbid / 12) * 128;
        bz = 0;
        Ahb = Tok; Bhb = Wkv; K = DKV;
    } else if (cls == 1) {
        int i = gbid - 96;
        bz = i / 48;
        int rem = i % 48;
        m0 = (rem / 6) * 128;          // q rows
        n0 = (rem % 6) * 128;          // dq cols (2 heads)
        Ahb = Qin + (size_t)bz * NQ * DQ; Bhb = Wq; K = DQ;
    } else {
        int i = gbid - 864;
        bz = i / 48;
        int rem = i % 48;
        m0 = (rem % 6) * 128;          // d rows
        n0 = (rem / 6) * 128;          // q cols
        Ahb = Wo; Bhb = g_o_h + (size_t)bz * NQ * DQ; K = DQ;
        // coarse wait for the 6 q-proj producers of this q-tile (R13 pattern)
        if (tid == 0) {
            volatile u32* f = &g_qdone[bz * 8 + (n0 >> 7)];
            while (*f < 6u) __nanosleep(64);
            __threadfence();
        }
        __syncthreads();
    }

    GEMM_MAINLOOP

    if (cls == 0) {
        // ---- kv epilogue: RoPE K / transpose V, publish ----
        if (n0 + wn < DQ) {
            #pragma unroll
            for (int mi = 0; mi < 2; mi++)
                #pragma unroll
                for (int ni = 0; ni < 4; ni++)
                    #pragma unroll
                    for (int half = 0; half < 2; half++) {
                        int m = m0 + wm + mi * 16 + (lane >> 2) + half * 8;
                        int bb = m >> 6, t = m & 63;
                        int n = n0 + wn + ni * 8 + (lane & 3) * 2;
                        int h = n >> 6;
                        int i0 = n & 63;
                        float2 cs0 = g_cs[t * 32 + i0];
                        float2 cs1 = g_cs[t * 32 + i0 + 1];
                        float x1a = acc[mi][ni][half*2],   x2a = acc[mi][ni+4][half*2];
                        float x1b = acc[mi][ni][half*2+1], x2b = acc[mi][ni+4][half*2+1];
                        float y1a = x1a * cs0.x - x2a * cs0.y;
                        float y2a = x2a * cs0.x + x1a * cs0.y;
                        float y1b = x1b * cs1.x - x2b * cs1.y;
                        float y2b = x2b * cs1.x + x1b * cs1.y;
                        size_t base = (((size_t)bb * NH + h) * NT + t) * HD;
                        *(u32*)&g_k_h[base + i0]      = pack_h(y1a, y1b);
                        *(u32*)&g_k_h[base + i0 + 32] = pack_h(y2a, y2b);
                    }
        } else {
            #pragma unroll
            for (int mi = 0; mi < 2; mi++)
                #pragma unroll
                for (int ni = 0; ni < 8; ni++)
                    #pragma unroll
                    for (int p = 0; p < 4; p++) {
                        int m = m0 + wm + mi * 16 + (lane >> 2) + (p >> 1) * 8;
                        int bb = m >> 6, t = m & 63;
                        int n = n0 + wn + ni * 8 + (lane & 3) * 2 + (p & 1);
                        int h = (n - DQ) >> 6;
                        int hd = n & 63;
                        size_t o = (((size_t)bb * NH + h) * HD + hd) * NT + t;
                        g_vT_h[o] = f16h(acc[mi][ni][p]);
                    }
        }
        __threadfence();
        __syncthreads();
        if (tid == 0) atomicAdd(&g_kvflag, 1u);
        return;
    }

    if (cls == 2) {
        // ---- out epilogue ----
        #pragma unroll
        for (int mi = 0; mi < 2; mi++)
            #pragma unroll
            for (int ni = 0; ni < 8; ni++) {
                int m = m0 + wm + mi * 16 + (lane >> 2);
                int n = n0 + wn + ni * 8 + (lane & 3) * 2;
                const float* c = acc[mi][ni];
                size_t a0 = ((size_t)bz * DQ + m) * NQ + n;
                size_t a1 = ((size_t)bz * DQ + m + 8) * NQ + n;
                float b0 = Bias[m], b1 = Bias[m + 8];
                float2 f0 = *(const float2*)&Feat[a0];
                float2 f1 = *(const float2*)&Feat[a1];
                *(float2*)&C[a0] = make_float2(c[0] + f0.x + b0, c[1] + f0.y + b0);
                *(float2*)&C[a1] = make_float2(c[2] + f1.x + b1, c[3] + f1.y + b1);
            }
        return;
    }

    // ---- q epilogue: RoPE -> smem, wait kv, attention, publish ----
    __syncthreads();

    const int hh_w = wid >> 2;
    const u32 qbase = sbase + QOFF + (u32)hh_w * 16384;
    #pragma unroll
    for (int mi = 0; mi < 2; mi++)
        #pragma unroll
        for (int ni = 0; ni < 4; ni++)
            #pragma unroll
            for (int half = 0; half < 2; half++) {
                int m_loc = wm + mi * 16 + (lane >> 2) + half * 8;
                int m = m0 + m_loc;
                int i0 = ni * 8 + (lane & 3) * 2;
                float2 cs0 = g_cs[m * 32 + i0];
                float2 cs1 = g_cs[m * 32 + i0 + 1];
                float x1a = acc[mi][ni][half*2],   x2a = acc[mi][ni+4][half*2];
                float x1b = acc[mi][ni][half*2+1], x2b = acc[mi][ni+4][half*2+1];
                float y1a = x1a * cs0.x - x2a * cs0.y;
                float y2a = x2a * cs0.x + x1a * cs0.y;
                float y1b = x1b * cs1.x - x2b * cs1.y;
                float y2b = x2b * cs1.x + x1b * cs1.y;
                asm volatile("st.shared.u32 [%0], %1;" ::
                    "r"(qbase + swz((u32)(m_loc * 128 + i0 * 2))), "r"(pack_h(y1a, y1b)));
                asm volatile("st.shared.u32 [%0], %1;" ::
                    "r"(qbase + swz((u32)(m_loc * 128 + (i0 + 32) * 2))), "r"(pack_h(y2a, y2b)));
            }

    if (tid == 0) {
        volatile u32* f = &g_kvflag;
        while (*f < 96u) __nanosleep(64);
        __threadfence();
    }
    __syncthreads();

    const int hbase = n0 >> 6;
    {
        size_t kvb = ((size_t)bz * NH + hbase) * (NT * HD);
        #pragma unroll
        for (int i = 0; i < 4; i++) {
            int c = i * 256 + tid;
            int hh = c >> 9;
            int r  = (c >> 3) & 63;
            int cc = c & 7;
            u32 off = (u32)hh * 8192 + swz((u32)(r * 128 + cc * 16));
            cpa16(sbase + KOFF + off, g_k_h  + kvb + (size_t)hh * (NT*HD) + r * HD + cc * 8);
            cpa16(sbase + VOFF + off, g_vT_h + kvb + (size_t)hh * (NT*HD) + r * HD + cc * 8);
        }
        CP_COMMIT();
        CP_WAIT(0);
        __syncthreads();
    }

    const u32 kbase = sbase + KOFF + (u32)hh_w * 8192;
    const u32 vbase = sbase + VOFF + (u32)hh_w * 8192;
    const int qw = (wid & 3) * 32;

    float s[2][8][4];
    #pragma unroll
    for (int i = 0; i < 2; i++)
        #pragma unroll
        for (int j = 0; j < 8; j++)
            #pragma unroll
            for (int p = 0; p < 4; p++) s[i][j][p] = 0.f;

    #pragma unroll
    for (int ks = 0; ks < 4; ks++) {
        u32 aq[2][4], bk[8][2];
        #pragma unroll
        for (int mi = 0; mi < 2; mi++) {
            int row = qw + mi * 16 + (lane & 15);
            int chunk = 2 * ks + (lane >> 4);
            ldsm4(aq[mi], qbase + swz((u32)(row * 128 + chunk * 16)));
        }
        #pragma unroll
        for (int jj = 0; jj < 4; jj++) {
            int g = lane >> 3;
            int row = (2 * jj + (g >> 1)) * 8 + (lane & 7);
            int chunk = 2 * ks + (g & 1);
            u32 t[4];
            ldsm4(t, kbase + swz((u32)(row * 128 + chunk * 16)));
            bk[2*jj][0] = t[0]; bk[2*jj][1] = t[1];
            bk[2*jj+1][0] = t[2]; bk[2*jj+1][1] = t[3];
        }
        #pragma unroll
        for (int mi = 0; mi < 2; mi++)
            #pragma unroll
            for (int ni = 0; ni < 8; ni++)
                mma16816(s[mi][ni], aq[mi], bk[ni]);
    }

    // softmax (scale 1/8)
    #pragma unroll
    for (int mi = 0; mi < 2; mi++) {
        float mx0 = -1e30f, mx1 = -1e30f;
        #pragma unroll
        for (int ni = 0; ni < 8; ni++) {
            #pragma unroll
            for (int p = 0; p < 4; p++) s[mi][ni][p] *= 0.125f;
            mx0 = fmaxf(mx0, fmaxf(s[mi][ni][0], s[mi][ni][1]));
            mx1 = fmaxf(mx1, fmaxf(s[mi][ni][2], s[mi][ni][3]));
        }
        mx0 = fmaxf(mx0, __shfl_xor_sync(0xffffffffu, mx0, 1));
        mx0 = fmaxf(mx0, __shfl_xor_sync(0xffffffffu, mx0, 2));
        mx1 = fmaxf(mx1, __shfl_xor_sync(0xffffffffu, mx1, 1));
        mx1 = fmaxf(mx1, __shfl_xor_sync(0xffffffffu, mx1, 2));
        float sm0 = 0.f, sm1 = 0.f;
        #pragma unroll
        for (int ni = 0; ni < 8; ni++) {
            s[mi][ni][0] = __expf(s[mi][ni][0] - mx0);
            s[mi][ni][1] = __expf(s[mi][ni][1] - mx0);
            s[mi][ni][2] = __expf(s[mi][ni][2] - mx1);
            s[mi][ni][3] = __expf(s[mi][ni][3] - mx1);
            sm0 += s[mi][ni][0] + s[mi][ni][1];
            sm1 += s[mi][ni][2] + s[mi][ni][3];
        }
        sm0 += __shfl_xor_sync(0xffffffffu, sm0, 1);
        sm0 += __shfl_xor_sync(0xffffffffu, sm0, 2);
        sm1 += __shfl_xor_sync(0xffffffffu, sm1, 1);
        sm1 += __shfl_xor_sync(0xffffffffu, sm1, 2);
        float i0 = 1.f / sm0, i1 = 1.f / sm1;
        #pragma unroll
        for (int ni = 0; ni < 8; ni++) {
            s[mi][ni][0] *= i0; s[mi][ni][1] *= i0;
            s[mi][ni][2] *= i1; s[mi][ni][3] *= i1;
        }
    }

    // O = P V
    float o[2][8][4];
    #pragma unroll
    for (int i = 0; i < 2; i++)
        #pragma unroll
        for (int j = 0; j < 8; j++)
            #pragma unroll
            for (int p = 0; p < 4; p++) o[i][j][p] = 0.f;

    #pragma unroll
    for (int kc = 0; kc < 4; kc++) {
        u32 pah[2][4], bv[8][2];
        #pragma unroll
        for (int mi = 0; mi < 2; mi++) {
            pah[mi][0] = pack_h(s[mi][2*kc][0],   s[mi][2*kc][1]);
            pah[mi][1] = pack_h(s[mi][2*kc][2],   s[mi][2*kc][3]);
            pah[mi][2] = pack_h(s[mi][2*kc+1][0], s[mi][2*kc+1][1]);
            pah[mi][3] = pack_h(s[mi][2*kc+1][2], s[mi][2*kc+1][3]);
        }
        #pragma unroll
        for (int jj = 0; jj < 4; jj++) {
            int g = lane >> 3;
            int row = (2 * jj + (g >> 1)) * 8 + (lane & 7);
            int chunk = 2 * kc + (g & 1);
            u32 t[4];
            ldsm4(t, vbase + swz((u32)(row * 128 + chunk * 16)));
            bv[2*jj][0] = t[0]; bv[2*jj][1] = t[1];
            bv[2*jj+1][0] = t[2]; bv[2*jj+1][1] = t[3];
        }
        #pragma unroll
        for (int mi = 0; mi < 2; mi++)
            #pragma unroll
            for (int ni = 0; ni < 8; ni++)
                mma16816(o[mi][ni], pah[mi], bv[ni]);
    }

    // store O hi fp16 at [B,Nq,Dq], then publish
    #pragma unroll
    for (int mi = 0; mi < 2; mi++)
        #pragma unroll
        for (int ni = 0; ni < 8; ni++) {
            int q = m0 + qw + mi * 16 + (lane >> 2);
            int col = n0 + hh_w * 64 + ni * 8 + (lane & 3) * 2;
            size_t a0 = ((size_t)(bz * NQ + q)) * DQ + col;
            size_t a1 = ((size_t)(bz * NQ + q + 8)) * DQ + col;
            *(u32*)&g_o_h[a0] = pack_h(o[mi][ni][0], o[mi][ni][1]);
            *(u32*)&g_o_h[a1] = pack_h(o[mi][ni][2], o[mi][ni][3]);
        }
    __threadfence();
    __syncthreads();
    if (tid == 0) atomicAdd(&g_qdone[bz * 8 + (m0 >> 7)], 1u);
}

// ---------------------------------------------------------------------------
// Launch
// ---------------------------------------------------------------------------
extern "C" void kernel_launch(void* const* d_in, const int* in_sizes, int n_in,
                              void* d_out, int out_size)
{
    (void)in_sizes; (void)n_in; (void)out_size;
    const float* feat   = (const float*)d_in[0];
    const float* tokens = (const float*)d_in[1];
    const float* Wq     = (const float*)d_in[2];
    const float* Wkv    = (const float*)d_in[3];
    const float* Wout   = (const float*)d_in[4];
    const float* bout   = (const float*)d_in[5];
    float* outp = (float*)d_out;

    u16 *pqih, *pwqh, *pwkh, *pwoh, *pth;
    cudaGetSymbolAddress((void**)&pqih, g_qin_h);
    cudaGetSymbolAddress((void**)&pwqh, g_wq_h);
    cudaGetSymbolAddress((void**)&pwkh, g_wkv_h);
    cudaGetSymbolAddress((void**)&pwoh, g_wo_h);
    cudaGetSymbolAddress((void**)&pth,  g_tok_h);

    cudaFuncSetAttribute(gemm_fused, cudaFuncAttributeMaxDynamicSharedMemorySize, GSMEM);

    // preprocessing at high occupancy (vectorized transposes, tokens, rope, flags)
    conv_all<<<944 + 3072, 256>>>(Wq, Wkv, Wout, tokens, feat);

    // fused: kv-proj -> q-proj + RoPE + attention -> out-proj (R13 structure)
    gemm_fused<<<96 + 768 + 768, 256, GSMEM>>>(
        pqih, pwqh, pth, pwkh, pwoh, outp, feat, bout);
}

// round 17
// speedup vs baseline: 1.2447x; 1.0013x over previous
#include <cuda_runtime.h>
#include <cuda_fp16.h>
#include <math.h>

// Problem constants
#define BATCH 16
#define DQ    768
#define NQ    1024
#define NT    64
#define DKV   384
#define NH    12
#define HD    64
#define NKV   (BATCH*NT)
#define DKV2  (2*DQ)

#define NEG_L2B_32 (-0.41524101186091903f)   // -log2(10000)/32
#define QSCALE     (0.18033688011115382f)    // 0.125 * log2(e), folded into q

typedef unsigned short u16;
typedef unsigned int   u32;

// ---------------------------------------------------------------------------
// Scratch (device globals)
// ---------------------------------------------------------------------------
__device__ __align__(16) u16 g_qin_h[(size_t)BATCH*NQ*DQ];     // feat^T hi fp16
__device__ __align__(16) u16 g_k_h  [(size_t)BATCH*NH*NT*HD];  // rope'd K hi [b,h,t,hd]
__device__ __align__(16) u16 g_vT_h [(size_t)BATCH*NH*HD*NT];  // V^T hi [b,h,hd,t]
__device__ __align__(16) u16 g_o_h  [(size_t)BATCH*NQ*DQ];     // attn out hi [B,Nq,Dq]
__device__ __align__(16) u16 g_wq_h [DQ*DQ];                   // WqT hi
__device__ __align__(16) u16 g_wkv_h[DKV2*DKV];                // WkvT hi
__device__ __align__(16) u16 g_wo_h [DQ*DQ];                   // WoutT hi
__device__ __align__(16) u16 g_tok_h[NKV*DKV];                 // tokens hi
__device__ __align__(16) float2 g_cs[NQ*32];                   // (cos, sin)
__device__ u32 g_kvflag = 0;                                   // kv-CTA done count
__device__ u32 g_qdone[BATCH * 8];                             // per (bz, qtile) done count

// ---------------------------------------------------------------------------
// Helpers (base-ISA only)
// ---------------------------------------------------------------------------
__device__ __forceinline__ u32 smem_u32(const void* p) {
    u32 a;
    asm("{ .reg .u64 t; cvta.to.shared.u64 t, %1; cvt.u32.u64 %0, t; }" : "=r"(a) : "l"(p));
    return a;
}
__device__ __forceinline__ u32 swz(u32 o) { return o ^ ((o >> 3) & 0x70); }

__device__ __forceinline__ void cpa16(u32 s, const void* g) {
    asm volatile("cp.async.cg.shared.global [%0], [%1], 16;" :: "r"(s), "l"(g) : "memory");
}
#define CP_COMMIT() asm volatile("cp.async.commit_group;" ::: "memory")
#define CP_WAIT(n)  asm volatile("cp.async.wait_group %0;" :: "n"(n) : "memory")

__device__ __forceinline__ void ldsm4(u32* r, u32 a) {
    asm volatile("ldmatrix.sync.aligned.m8n8.x4.shared.b16 {%0,%1,%2,%3}, [%4];"
                 : "=r"(r[0]), "=r"(r[1]), "=r"(r[2]), "=r"(r[3]) : "r"(a));
}
__device__ __forceinline__ void mma16816(float* c, const u32* a, const u32* b) {
    asm volatile(
        "mma.sync.aligned.m16n8k16.row.col.f32.f16.f16.f32 "
        "{%0,%1,%2,%3}, {%4,%5,%6,%7}, {%8,%9}, {%0,%1,%2,%3};"
        : "+f"(c[0]), "+f"(c[1]), "+f"(c[2]), "+f"(c[3])
        : "r"(a[0]), "r"(a[1]), "r"(a[2]), "r"(a[3]), "r"(b[0]), "r"(b[1]));
}

__device__ __forceinline__ u16 f16h(float v) {
    __half h = __float2half_rn(v);
    return *reinterpret_cast<u16*>(&h);
}
__device__ __forceinline__ u32 pack_h(float a, float b) {
    __half2 h = __float22half2_rn(make_float2(a, b));
    return *reinterpret_cast<u32*>(&h);
}

// ---------------------------------------------------------------------------
// Prep kernel: vectorized 64x64 transposes (weights + feat), tokens, rope, flags
// Block ranges: [0,144) Wq | [144,288) Wkv | [288,432) Wout |
//               [432,816) tokens | [816,944) rope+flags | [944,944+3072) feat
// ---------------------------------------------------------------------------
__device__ __forceinline__ void conv_T64(const float* __restrict__ in,
                                         u16* __restrict__ out,
                                         int ld_in, int ld_out,
                                         int bd, int bn, float (*t)[65])
{
    const int tid = threadIdx.x;
    #pragma unroll
    for (int it = 0; it < 4; it++) {
        int idx = it * 256 + tid;
        int r = idx >> 4, c4 = idx & 15;
        float4 v = *(const float4*)(in + (size_t)(bd * 64 + r) * ld_in + bn * 64 + c4 * 4);
        t[r][c4 * 4 + 0] = v.x; t[r][c4 * 4 + 1] = v.y;
        t[r][c4 * 4 + 2] = v.z; t[r][c4 * 4 + 3] = v.w;
    }
    __syncthreads();
    #pragma unroll
    for (int it = 0; it < 2; it++) {
        int idx = it * 256 + tid;
        int r = idx >> 3, c = idx & 7;
        u32 w0 = pack_h(t[c * 8 + 0][r], t[c * 8 + 1][r]);
        u32 w1 = pack_h(t[c * 8 + 2][r], t[c * 8 + 3][r]);
        u32 w2 = pack_h(t[c * 8 + 4][r], t[c * 8 + 5][r]);
        u32 w3 = pack_h(t[c * 8 + 6][r], t[c * 8 + 7][r]);
        *(uint4*)(out + (size_t)(bn * 64 + r) * ld_out + bd * 64 + c * 8) =
            make_uint4(w0, w1, w2, w3);
    }
}

__global__ void __launch_bounds__(256)
conv_all(const float* __restrict__ Wq, const float* __restrict__ Wkv,
         const float* __restrict__ Wout, const float* __restrict__ tok,
         const float* __restrict__ feat)
{
    __shared__ float tbuf[64 * 65];
    int bid = blockIdx.x;
    if (bid < 144) {
        conv_T64(Wq, g_wq_h, DQ, DQ, bid / 12, bid % 12, (float(*)[65])tbuf);
    } else if (bid < 288) {
        int i = bid - 144;
        conv_T64(Wkv, g_wkv_h, DKV2, DKV, i / 24, i % 24, (float(*)[65])tbuf);
    } else if (bid < 432) {
        int i = bid - 288;
        conv_T64(Wout, g_wo_h, DQ, DQ, i / 12, i % 12, (float(*)[65])tbuf);
    } else if (bid < 816) {
        int base = (bid - 432) * 1024 + threadIdx.x * 4;
        float4 v = *(const float4*)(tok + base);
        *(u32*)&g_tok_h[base]     = pack_h(v.x, v.y);
        *(u32*)&g_tok_h[base + 2] = pack_h(v.z, v.w);
    } else if (bid < 944) {
        if (bid == 816) {
            if (threadIdx.x == 0) g_kvflag = 0;
            if (threadIdx.x < BATCH * 8) g_qdone[threadIdx.x] = 0;
        }
        int idx = (bid - 816) * 256 + threadIdx.x;
        int pos = idx >> 5, i = idx & 31;
        float inv = exp2f((float)i * NEG_L2B_32);
        float sn, cs;
        sincosf((float)pos * inv, &sn, &cs);
        g_cs[idx] = make_float2(cs, sn);
    } else {
        int i = bid - 944;             // 3072 blocks: 16 z x 12 bd x 16 bn
        int z = i / 192;
        int rem = i % 192;
        int bd = rem >> 4;
        int bn = rem & 15;
        conv_T64(feat + (size_t)z * DQ * NQ, g_qin_h + (size_t)z * NQ * DQ,
                 NQ, DQ, bd, bn, (float(*)[65])tbuf);
    }
}

// ---------------------------------------------------------------------------
// Shared GEMM config
// ---------------------------------------------------------------------------
#define BK 64
#define STG 32768
#define AH_O 0
#define BH_O 16384
#define GSMEM (3*STG)
#define QOFF 0
#define KOFF 32768
#define VOFF 49152

#define GEMM_PREAMBLE                                                            \
    extern __shared__ char smdyn[];                                              \
    const u32 sbase = smem_u32(smdyn);                                           \
    const int tid  = threadIdx.x;                                                \
    const int lane = tid & 31;                                                   \
    const int wid  = tid >> 5;                                                   \
    const int wm   = (wid & 3) * 32;                                             \
    const int wn   = (wid >> 2) * 64;

#define LOAD_STAGE(kt, slot) do {                                                \
    u32 so_ = sbase + (u32)(slot) * STG;                                         \
    int k0_ = (kt) * BK;                                                         \
    _Pragma("unroll")                                                            \
    for (int i_ = 0; i_ < 4; i_++) {                                             \
        int chunk_ = i_ * 256 + tid;                                             \
        int row_ = chunk_ >> 3, c_ = chunk_ & 7;                                 \
        u32 off_ = swz((u32)(row_ * 128 + c_ * 16));                             \
        size_t ga_ = (size_t)(m0 + row_) * K + k0_ + c_ * 8;                     \
        size_t gb_ = (size_t)(n0 + row_) * K + k0_ + c_ * 8;                     \
        cpa16(so_ + AH_O + off_, Ahb + ga_);                                     \
        cpa16(so_ + BH_O + off_, Bhb + gb_);                                     \
    }                                                                            \
} while (0)

#define LOAD_FRAGS(buf, sa, ks) do {                                             \
    _Pragma("unroll")                                                            \
    for (int mi_ = 0; mi_ < 2; mi_++) {                                          \
        int row_ = wm + mi_ * 16 + (lane & 15);                                  \
        int chunk_ = 2 * (ks) + (lane >> 4);                                     \
        ldsm4(ahf[buf][mi_], (sa) + AH_O + swz((u32)(row_ * 128 + chunk_ * 16))); \
    }                                                                            \
    _Pragma("unroll")                                                            \
    for (int jj_ = 0; jj_ < 4; jj_++) {                                          \
        int g_ = lane >> 3;                                                      \
        int row_ = wn + (2 * jj_ + (g_ >> 1)) * 8 + (lane & 7);                  \
        int chunk_ = 2 * (ks) + (g_ & 1);                                        \
        u32 t_[4];                                                               \
        ldsm4(t_, (sa) + BH_O + swz((u32)(row_ * 128 + chunk_ * 16)));           \
        bhf[buf][2*jj_][0] = t_[0]; bhf[buf][2*jj_][1] = t_[1];                  \
        bhf[buf][2*jj_+1][0] = t_[2]; bhf[buf][2*jj_+1][1] = t_[3];              \
    }                                                                            \
} while (0)

#define GEMM_MAINLOOP                                                            \
    float acc[2][8][4];                                                          \
    _Pragma("unroll")                                                            \
    for (int i = 0; i < 2; i++)                                                  \
        _Pragma("unroll")                                                        \
        for (int j = 0; j < 8; j++)                                              \
            _Pragma("unroll")                                                    \
            for (int p = 0; p < 4; p++) acc[i][j][p] = 0.f;                      \
    const int KT = K / BK;                                                       \
    LOAD_STAGE(0, 0);                                                            \
    CP_COMMIT();                                                                 \
    if (KT > 1) { LOAD_STAGE(1, 1); CP_COMMIT(); }                               \
    u32 ahf[2][2][4], bhf[2][8][2];                                              \
    int slot = 0;                                                                \
    for (int kt = 0; kt < KT; kt++) {                                            \
        if (kt + 1 < KT) CP_WAIT(1); else CP_WAIT(0);                            \
        __syncthreads();                                                         \
        if (kt + 2 < KT) {                                                       \
            int ns = slot + 2; if (ns >= 3) ns -= 3;                             \
            LOAD_STAGE(kt + 2, ns);                                              \
            CP_COMMIT();                                                         \
        }                                                                        \
        const u32 sa = sbase + (u32)slot * STG;                                  \
        LOAD_FRAGS(0, sa, 0);                                                    \
        _Pragma("unroll")                                                        \
        for (int ks = 0; ks < 4; ks++) {                                         \
            const int cur = ks & 1;                                              \
            if (ks < 3) LOAD_FRAGS(!cur ? 1 : 0, sa, ks + 1);                    \
            _Pragma("unroll")                                                    \
            for (int mi = 0; mi < 2; mi++)                                       \
                _Pragma("unroll")                                                \
                for (int ni = 0; ni < 8; ni++)                                   \
                    mma16816(acc[mi][ni], ahf[cur][mi], bhf[cur][ni]);           \
        }                                                                        \
        slot++; if (slot >= 3) slot = 0;                                         \
    }

// ---------------------------------------------------------------------------
// Fused kernel: kv-proj (96) -> q-proj+attention (768) -> out-proj (768)
// ---------------------------------------------------------------------------
__global__ void __launch_bounds__(256, 2)
gemm_fused(const u16* __restrict__ Qin, const u16* __restrict__ Wq,
           const u16* __restrict__ Tok, const u16* __restrict__ Wkv,
           const u16* __restrict__ Wo,
           float* __restrict__ C, const float* __restrict__ Feat,
           const float* __restrict__ Bias)
{
    GEMM_PREAMBLE
    const int gbid = blockIdx.x;
    const int cls = (gbid < 96) ? 0 : (gbid < 864 ? 1 : 2);
    int m0, n0, bz, K;
    const u16 *Ahb, *Bhb;
    if (cls == 0) {
        n0 = (gbid % 12) * 128;
        m0 = (gbid / 12) * 128;
        bz = 0;
        Ahb = Tok; Bhb = Wkv; K = DKV;
    } else if (cls == 1) {
        int i = gbid - 96;
        bz = i / 48;
        int rem = i % 48;
        m0 = (rem / 6) * 128;          // q rows
        n0 = (rem % 6) * 128;          // dq cols (2 heads)
        Ahb = Qin + (size_t)bz * NQ * DQ; Bhb = Wq; K = DQ;
    } else {
        int i = gbid - 864;
        bz = i / 48;
        int rem = i % 48;
        m0 = (rem % 6) * 128;          // d rows
        n0 = (rem / 6) * 128;          // q cols
        Ahb = Wo; Bhb = g_o_h + (size_t)bz * NQ * DQ; K = DQ;
        // coarse wait for the 6 q-proj producers of this q-tile
        if (tid == 0) {
            volatile u32* f = &g_qdone[bz * 8 + (n0 >> 7)];
            while (*f < 6u) __nanosleep(64);
            __threadfence();
        }
        __syncthreads();
    }

    GEMM_MAINLOOP

    if (cls == 0) {
        // ---- kv epilogue: RoPE K / transpose V, publish ----
        if (n0 + wn < DQ) {
            #pragma unroll
            for (int mi = 0; mi < 2; mi++)
                #pragma unroll
                for (int ni = 0; ni < 4; ni++)
                    #pragma unroll
                    for (int half = 0; half < 2; half++) {
                        int m = m0 + wm + mi * 16 + (lane >> 2) + half * 8;
                        int bb = m >> 6, t = m & 63;
                        int n = n0 + wn + ni * 8 + (lane & 3) * 2;
                        int h = n >> 6;
                        int i0 = n & 63;
                        float2 cs0 = g_cs[t * 32 + i0];
                        float2 cs1 = g_cs[t * 32 + i0 + 1];
                        float x1a = acc[mi][ni][half*2],   x2a = acc[mi][ni+4][half*2];
                        float x1b = acc[mi][ni][half*2+1], x2b = acc[mi][ni+4][half*2+1];
                        float y1a = x1a * cs0.x - x2a * cs0.y;
                        float y2a = x2a * cs0.x + x1a * cs0.y;
                        float y1b = x1b * cs1.x - x2b * cs1.y;
                        float y2b = x2b * cs1.x + x1b * cs1.y;
                        size_t base = (((size_t)bb * NH + h) * NT + t) * HD;
                        *(u32*)&g_k_h[base + i0]      = pack_h(y1a, y1b);
                        *(u32*)&g_k_h[base + i0 + 32] = pack_h(y2a, y2b);
                    }
        } else {
            #pragma unroll
            for (int mi = 0; mi < 2; mi++)
                #pragma unroll
                for (int ni = 0; ni < 8; ni++)
                    #pragma unroll
                    for (int p = 0; p < 4; p++) {
                        int m = m0 + wm + mi * 16 + (lane >> 2) + (p >> 1) * 8;
                        int bb = m >> 6, t = m & 63;
                        int n = n0 + wn + ni * 8 + (lane & 3) * 2 + (p & 1);
                        int h = (n - DQ) >> 6;
                        int hd = n & 63;
                        size_t o = (((size_t)bb * NH + h) * HD + hd) * NT + t;
                        g_vT_h[o] = f16h(acc[mi][ni][p]);
                    }
        }
        __threadfence();
        __syncthreads();
        if (tid == 0) atomicAdd(&g_kvflag, 1u);
        return;
    }

    if (cls == 2) {
        // ---- out epilogue ----
        #pragma unroll
        for (int mi = 0; mi < 2; mi++)
            #pragma unroll
            for (int ni = 0; ni < 8; ni++) {
                int m = m0 + wm + mi * 16 + (lane >> 2);
                int n = n0 + wn + ni * 8 + (lane & 3) * 2;
                const float* c = acc[mi][ni];
                size_t a0 = ((size_t)bz * DQ + m) * NQ + n;
                size_t a1 = ((size_t)bz * DQ + m + 8) * NQ + n;
                float b0 = Bias[m], b1 = Bias[m + 8];
                float2 f0 = *(const float2*)&Feat[a0];
                float2 f1 = *(const float2*)&Feat[a1];
                *(float2*)&C[a0] = make_float2(c[0] + f0.x + b0, c[1] + f0.y + b0);
                *(float2*)&C[a1] = make_float2(c[2] + f1.x + b1, c[3] + f1.y + b1);
            }
        return;
    }

    // ---- q epilogue: RoPE (+ folded softmax scale) -> smem, wait kv, attention ----
    __syncthreads();

    const int hh_w = wid >> 2;
    const u32 qbase = sbase + QOFF + (u32)hh_w * 16384;
    #pragma unroll
    for (int mi = 0; mi < 2; mi++)
        #pragma unroll
        for (int ni = 0; ni < 4; ni++)
            #pragma unroll
            for (int half = 0; half < 2; half++) {
                int m_loc = wm + mi * 16 + (lane >> 2) + half * 8;
                int m = m0 + m_loc;
                int i0 = ni * 8 + (lane & 3) * 2;
                float2 cs0 = g_cs[m * 32 + i0];
                float2 cs1 = g_cs[m * 32 + i0 + 1];
                float x1a = acc[mi][ni][half*2],   x2a = acc[mi][ni+4][half*2];
                float x1b = acc[mi][ni][half*2+1], x2b = acc[mi][ni+4][half*2+1];
                // RoPE with folded 0.125*log2(e) scale (softmax in log2 domain)
                float y1a = (x1a * cs0.x - x2a * cs0.y) * QSCALE;
                float y2a = (x2a * cs0.x + x1a * cs0.y) * QSCALE;
                float y1b = (x1b * cs1.x - x2b * cs1.y) * QSCALE;
                float y2b = (x2b * cs1.x + x1b * cs1.y) * QSCALE;
                asm volatile("st.shared.u32 [%0], %1;" ::
                    "r"(qbase + swz((u32)(m_loc * 128 + i0 * 2))), "r"(pack_h(y1a, y1b)));
                asm volatile("st.shared.u32 [%0], %1;" ::
                    "r"(qbase + swz((u32)(m_loc * 128 + (i0 + 32) * 2))), "r"(pack_h(y2a, y2b)));
            }

    if (tid == 0) {
        volatile u32* f = &g_kvflag;
        while (*f < 96u) __nanosleep(64);
        __threadfence();
    }
    __syncthreads();

    const int hbase = n0 >> 6;
    {
        size_t kvb = ((size_t)bz * NH + hbase) * (NT * HD);
        #pragma unroll
        for (int i = 0; i < 4; i++) {
            int c = i * 256 + tid;
            int hh = c >> 9;
            int r  = (c >> 3) & 63;
            int cc = c & 7;
            u32 off = (u32)hh * 8192 + swz((u32)(r * 128 + cc * 16));
            cpa16(sbase + KOFF + off, g_k_h  + kvb + (size_t)hh * (NT*HD) + r * HD + cc * 8);
            cpa16(sbase + VOFF + off, g_vT_h + kvb + (size_t)hh * (NT*HD) + r * HD + cc * 8);
        }
        CP_COMMIT();
        CP_WAIT(0);
        __syncthreads();
    }

    const u32 kbase = sbase + KOFF + (u32)hh_w * 8192;
    const u32 vbase = sbase + VOFF + (u32)hh_w * 8192;
    const int qw = (wid & 3) * 32;

    float s[2][8][4];
    #pragma unroll
    for (int i = 0; i < 2; i++)
        #pragma unroll
        for (int j = 0; j < 8; j++)
            #pragma unroll
            for (int p = 0; p < 4; p++) s[i][j][p] = 0.f;

    #pragma unroll
    for (int ks = 0; ks < 4; ks++) {
        u32 aq[2][4], bk[8][2];
        #pragma unroll
        for (int mi = 0; mi < 2; mi++) {
            int row = qw + mi * 16 + (lane & 15);
            int chunk = 2 * ks + (lane >> 4);
            ldsm4(aq[mi], qbase + swz((u32)(row * 128 + chunk * 16)));
        }
        #pragma unroll
        for (int jj = 0; jj < 4; jj++) {
            int g = lane >> 3;
            int row = (2 * jj + (g >> 1)) * 8 + (lane & 7);
            int chunk = 2 * ks + (g & 1);
            u32 t[4];
            ldsm4(t, kbase + swz((u32)(row * 128 + chunk * 16)));
            bk[2*jj][0] = t[0]; bk[2*jj][1] = t[1];
            bk[2*jj+1][0] = t[2]; bk[2*jj+1][1] = t[3];
        }
        #pragma unroll
        for (int mi = 0; mi < 2; mi++)
            #pragma unroll
            for (int ni = 0; ni < 8; ni++)
                mma16816(s[mi][ni], aq[mi], bk[ni]);
    }

    // softmax in log2 domain (scale already folded into q)
    #pragma unroll
    for (int mi = 0; mi < 2; mi++) {
        float mx0 = -1e30f, mx1 = -1e30f;
        #pragma unroll
        for (int ni = 0; ni < 8; ni++) {
            mx0 = fmaxf(mx0, fmaxf(s[mi][ni][0], s[mi][ni][1]));
            mx1 = fmaxf(mx1, fmaxf(s[mi][ni][2], s[mi][ni][3]));
        }
        mx0 = fmaxf(mx0, __shfl_xor_sync(0xffffffffu, mx0, 1));
        mx0 = fmaxf(mx0, __shfl_xor_sync(0xffffffffu, mx0, 2));
        mx1 = fmaxf(mx1, __shfl_xor_sync(0xffffffffu, mx1, 1));
        mx1 = fmaxf(mx1, __shfl_xor_sync(0xffffffffu, mx1, 2));
        float sm0 = 0.f, sm1 = 0.f;
        #pragma unroll
        for (int ni = 0; ni < 8; ni++) {
            s[mi][ni][0] = exp2f(s[mi][ni][0] - mx0);
            s[mi][ni][1] = exp2f(s[mi][ni][1] - mx0);
            s[mi][ni][2] = exp2f(s[mi][ni][2] - mx1);
            s[mi][ni][3] = exp2f(s[mi][ni][3] - mx1);
            sm0 += s[mi][ni][0] + s[mi][ni][1];
            sm1 += s[mi][ni][2] + s[mi][ni][3];
        }
        sm0 += __shfl_xor_sync(0xffffffffu, sm0, 1);
        sm0 += __shfl_xor_sync(0xffffffffu, sm0, 2);
        sm1 += __shfl_xor_sync(0xffffffffu, sm1, 1);
        sm1 += __shfl_xor_sync(0xffffffffu, sm1, 2);
        float i0 = 1.f / sm0, i1 = 1.f / sm1;
        #pragma unroll
        for (int ni = 0; ni < 8; ni++) {
            s[mi][ni][0] *= i0; s[mi][ni][1] *= i0;
            s[mi][ni][2] *= i1; s[mi][ni][3] *= i1;
        }
    }

    // O = P V
    float o[2][8][4];
    #pragma unroll
    for (int i = 0; i < 2; i++)
        #pragma unroll
        for (int j = 0; j < 8; j++)
            #pragma unroll
            for (int p = 0; p < 4; p++) o[i][j][p] = 0.f;

    #pragma unroll
    for (int kc = 0; kc < 4; kc++) {
        u32 pah[2][4], bv[8][2];
        #pragma unroll
        for (int mi = 0; mi < 2; mi++) {
            pah[mi][0] = pack_h(s[mi][2*kc][0],   s[mi][2*kc][1]);
            pah[mi][1] = pack_h(s[mi][2*kc][2],   s[mi][2*kc][3]);
            pah[mi][2] = pack_h(s[mi][2*kc+1][0], s[mi][2*kc+1][1]);
            pah[mi][3] = pack_h(s[mi][2*kc+1][2], s[mi][2*kc+1][3]);
        }
        #pragma unroll
        for (int jj = 0; jj < 4; jj++) {
            int g = lane >> 3;
            int row = (2 * jj + (g >> 1)) * 8 + (lane & 7);
            int chunk = 2 * kc + (g & 1);
            u32 t[4];
            ldsm4(t, vbase + swz((u32)(row * 128 + chunk * 16)));
            bv[2*jj][0] = t[0]; bv[2*jj][1] = t[1];
            bv[2*jj+1][0] = t[2]; bv[2*jj+1][1] = t[3];
        }
        #pragma unroll
        for (int mi = 0; mi < 2; mi++)
            #pragma unroll
            for (int ni = 0; ni < 8; ni++)
                mma16816(o[mi][ni], pah[mi], bv[ni]);
    }

    // store O hi fp16 at [B,Nq,Dq], then publish
    #pragma unroll
    for (int mi = 0; mi < 2; mi++)
        #pragma unroll
        for (int ni = 0; ni < 8; ni++) {
            int q = m0 + qw + mi * 16 + (lane >> 2);
            int col = n0 + hh_w * 64 + ni * 8 + (lane & 3) * 2;
            size_t a0 = ((size_t)(bz * NQ + q)) * DQ + col;
            size_t a1 = ((size_t)(bz * NQ + q + 8)) * DQ + col;
            *(u32*)&g_o_h[a0] = pack_h(o[mi][ni][0], o[mi][ni][1]);
            *(u32*)&g_o_h[a1] = pack_h(o[mi][ni][2], o[mi][ni][3]);
        }
    __threadfence();
    __syncthreads();
    if (tid == 0) atomicAdd(&g_qdone[bz * 8 + (m0 >> 7)], 1u);
}

// ---------------------------------------------------------------------------
// Launch
// ---------------------------------------------------------------------------
extern "C" void kernel_launch(void* const* d_in, const int* in_sizes, int n_in,
                              void* d_out, int out_size)
{
    (void)in_sizes; (void)n_in; (void)out_size;
    const float* feat   = (const float*)d_in[0];
    const float* tokens = (const float*)d_in[1];
    const float* Wq     = (const float*)d_in[2];
    const float* Wkv    = (const float*)d_in[3];
    const float* Wout   = (const float*)d_in[4];
    const float* bout   = (const float*)d_in[5];
    float* outp = (float*)d_out;

    u16 *pqih, *pwqh, *pwkh, *pwoh, *pth;
    cudaGetSymbolAddress((void**)&pqih, g_qin_h);
    cudaGetSymbolAddress((void**)&pwqh, g_wq_h);
    cudaGetSymbolAddress((void**)&pwkh, g_wkv_h);
    cudaGetSymbolAddress((void**)&pwoh, g_wo_h);
    cudaGetSymbolAddress((void**)&pth,  g_tok_h);

    cudaFuncSetAttribute(gemm_fused, cudaFuncAttributeMaxDynamicSharedMemorySize, GSMEM);

    // preprocessing at high occupancy (vectorized transposes, tokens, rope, flags)
    conv_all<<<944 + 3072, 256>>>(Wq, Wkv, Wout, tokens, feat);

    // fused: kv-proj -> q-proj + RoPE + attention -> out-proj
    gemm_fused<<<96 + 768 + 768, 256, GSMEM>>>(
        pqih, pwqh, pth, pwkh, pwoh, outp, feat, bout);
}